// round 11
// baseline (speedup 1.0000x reference)
#include <cuda_runtime.h>
#include <cstdint>

#define K 128

typedef unsigned long long ull;

// ---------------- persistent device scratch ----------------
__device__ float g_A[K * K];      // A[i][j] = sum_o Wq[o,i]*Wk[o,j] / sqrt(128)
__device__ float g_M0[K * K];     // [k][o] layout
__device__ float g_M1[K * K];     // [k][o] layout
__device__ float g_tb[K];         // (conv_b-mean)*scale + beta
__device__ float g_w[32768 * 4];  // attention weights per (b,s)

// ---------------- packed f32x2 helpers ----------------
__device__ __forceinline__ ull pack_dup(float v) {
    unsigned u = __float_as_uint(v);
    ull r;
    asm("mov.b64 %0, {%1, %1};" : "=l"(r) : "r"(u));
    return r;
}
__device__ __forceinline__ void fma2(ull& acc, ull a, ull b) {
    asm("fma.rn.f32x2 %0, %1, %2, %0;" : "+l"(acc) : "l"(a), "l"(b));
}
__device__ __forceinline__ float f2lo(ull v) { return __uint_as_float((unsigned)v); }
__device__ __forceinline__ float f2hi(ull v) { return __uint_as_float((unsigned)(v >> 32)); }

// ---------------- setup: build A, M0[k][o], M1[k][o], tb ----------------
__global__ __launch_bounds__(256) void setup_kernel(
    const float* __restrict__ Wq, const float* __restrict__ Wk, const float* __restrict__ Wv,
    const float* __restrict__ conv_w, const float* __restrict__ conv_b,
    const float* __restrict__ gamma, const float* __restrict__ beta,
    const float* __restrict__ mean, const float* __restrict__ var) {
    const int m = blockIdx.y;   // 0: A, 1: M0, 2: M1
    const int r = blockIdx.x;   // i for A, o for M
    const int t = threadIdx.x;  // 256
    const int j = t & 127, h = t >> 7;
    __shared__ float row[K];
    __shared__ float red[256];
    if (m == 0) {
        if (t < K) row[t] = Wq[t * K + r];
        __syncthreads();
        float acc = 0.f;
        const int o0 = h * 64;
#pragma unroll 8
        for (int o = 0; o < 64; ++o) acc += row[o0 + o] * Wk[(o0 + o) * K + j];
        red[t] = acc;
        __syncthreads();
        if (t < K) g_A[r * K + t] = (red[t] + red[t + 128]) * 0.08838834764831845f;
    } else {
        if (t < K) row[t] = conv_w[r * 256 + (m == 2 ? K : 0) + t];
        __syncthreads();
        float acc = 0.f;
        const int c0 = h * 64;
#pragma unroll 8
        for (int c = 0; c < 64; ++c) acc += row[c0 + c] * Wv[(c0 + c) * K + j];
        red[t] = acc;
        __syncthreads();
        if (t < K) {
            const float sc = gamma[r] * rsqrtf(var[r] + 1e-5f);
            const float val = (red[t] + red[t + 128]) * sc * 0.7071067811865476f;
            if (m == 1) {
                g_M0[t * K + r] = val;  // [k][o]
                if (t == 0) g_tb[r] = (conv_b[r] - mean[r]) * sc + beta[r];
            } else {
                g_M1[t * K + r] = val;
            }
        }
    }
}

// ---------------- attention: fused P-GEMM + dot + softmax ----------------
// chunk = 64 b. 8 warps = (jh 0..3: 32-j block) x (ih 0..1: 64-i half).
// lane covers b=lane and b=lane+32. dot is linear in P partials -> per-warp
// partial dots reduced across the 8 warps in smem.
__global__ __launch_bounds__(256, 2) void attn_kernel(const float* __restrict__ x,
                                                      const float* __restrict__ y, int B) {
    extern __shared__ float sm[];
    float* sA = sm;              // 16384 floats
    float* sY = sA + 16384;      // [i][b] : 128*64 = 8192
    float* sD = sY + 8192;       // 8 warps * 64 b * 4 s = 2048
    const int t = threadIdx.x;
    const int lane = t & 31, w = t >> 5;
    const int jh = w & 3, ih = w >> 2;

    for (int i = t; i < 4096; i += 256) ((float4*)sA)[i] = ((const float4*)g_A)[i];

    const int nch = B >> 6;
    for (int ch = blockIdx.x; ch < nch; ch += gridDim.x) {
        const int b0 = ch << 6;
        __syncthreads();
        // stage y transposed: sY[i][b]
        {
            const int b = t >> 2, iq = t & 3;
            const float4* yp = (const float4*)(y + (size_t)(b0 + b) * K + iq * 32);
            float4 v[8];
#pragma unroll
            for (int q = 0; q < 8; ++q) v[q] = yp[q];
#pragma unroll
            for (int q = 0; q < 8; ++q) {
                const int i = iq * 32 + q * 4;
                sY[(i + 0) * 64 + b] = v[q].x;
                sY[(i + 1) * 64 + b] = v[q].y;
                sY[(i + 2) * 64 + b] = v[q].z;
                sY[(i + 3) * 64 + b] = v[q].w;
            }
        }
        __syncthreads();

        // P partial GEMM over this warp's (j-block, i-half)
        ull acc0[16], acc1[16];
#pragma unroll
        for (int p = 0; p < 16; ++p) { acc0[p] = 0; acc1[p] = 0; }
        {
            const float* Arow = sA + (ih * 64) * K + jh * 32;
            const float* Yrow = sY + (ih * 64) * 64;
#pragma unroll 2
            for (int i = 0; i < 64; ++i) {
                const ull y0 = pack_dup(Yrow[i * 64 + lane]);
                const ull y1 = pack_dup(Yrow[i * 64 + lane + 32]);
                const ulonglong2* ap = (const ulonglong2*)(Arow + i * K);
#pragma unroll
                for (int p = 0; p < 8; ++p) {
                    const ulonglong2 av = ap[p];
                    fma2(acc0[2 * p], av.x, y0);
                    fma2(acc0[2 * p + 1], av.y, y0);
                    fma2(acc1[2 * p], av.x, y1);
                    fma2(acc1[2 * p + 1], av.y, y1);
                }
            }
        }

        // partial dots with x over this j-block
        {
            float d0[4], d1[4];
            const float* xb0 = x + ((size_t)(b0 + lane)) * 4 * K + jh * 32;
#pragma unroll
            for (int s = 0; s < 4; ++s) {
                const ulonglong2* xp = (const ulonglong2*)(xb0 + s * K);
                ull da = 0;
#pragma unroll
                for (int p = 0; p < 8; ++p) {
                    const ulonglong2 xv = xp[p];
                    fma2(da, acc0[2 * p], xv.x);
                    fma2(da, acc0[2 * p + 1], xv.y);
                }
                d0[s] = f2lo(da) + f2hi(da);
            }
            const float* xb1 = x + ((size_t)(b0 + lane + 32)) * 4 * K + jh * 32;
#pragma unroll
            for (int s = 0; s < 4; ++s) {
                const ulonglong2* xp = (const ulonglong2*)(xb1 + s * K);
                ull da = 0;
#pragma unroll
                for (int p = 0; p < 8; ++p) {
                    const ulonglong2 xv = xp[p];
                    fma2(da, acc1[2 * p], xv.x);
                    fma2(da, acc1[2 * p + 1], xv.y);
                }
                d1[s] = f2lo(da) + f2hi(da);
            }
            ((float4*)sD)[w * 64 + lane] = make_float4(d0[0], d0[1], d0[2], d0[3]);
            ((float4*)sD)[w * 64 + lane + 32] = make_float4(d1[0], d1[1], d1[2], d1[3]);
        }
        __syncthreads();

        if (t < 64) {
            float4 s0 = make_float4(0.f, 0.f, 0.f, 0.f);
#pragma unroll
            for (int ww = 0; ww < 8; ++ww) {
                const float4 v = ((const float4*)sD)[ww * 64 + t];
                s0.x += v.x; s0.y += v.y; s0.z += v.z; s0.w += v.w;
            }
            const float mx = fmaxf(fmaxf(s0.x, s0.y), fmaxf(s0.z, s0.w));
            const float e0 = expf(s0.x - mx), e1 = expf(s0.y - mx);
            const float e2 = expf(s0.z - mx), e3 = expf(s0.w - mx);
            const float inv = 1.f / (e0 + e1 + e2 + e3);
            ((float4*)g_w)[b0 + t] = make_float4(e0 * inv, e1 * inv, e2 * inv, e3 * inv);
        }
    }
}

// ---------------- z kernel: c-vectors + GEMM + BN + leaky ----------------
// chunk = 32 b. 16 warps: warp w -> o-block [w*8, w*8+8). lane = b.
// sM0/sM1 [k][o] so LDS.128 broadcast gives f32x2 o-pairs directly.
__global__ __launch_bounds__(512) void z_kernel(const float* __restrict__ x,
                                                float* __restrict__ out, int B) {
    extern __shared__ float sm[];
    float* sM0 = sm;            // 16384
    float* sM1 = sM0 + 16384;   // 16384
    float4* sC = (float4*)(sM1 + 16384);  // [k][b] float4 (cA0,cA1,cB0,cB1): 128*32
    const int t = threadIdx.x;
    const int lane = t & 31, w = t >> 5;  // w: 0..15 (= kq in build phase)

    for (int i = t; i < 4096; i += 512) {
        ((float4*)sM0)[i] = ((const float4*)g_M0)[i];
        ((float4*)sM1)[i] = ((const float4*)g_M1)[i];
    }
    const int o0 = w * 8;
    float tb[8];
#pragma unroll
    for (int q = 0; q < 8; ++q) tb[q] = g_tb[o0 + q];

    const int nch = B >> 5;  // 1024
    float4 xv[8];
    float4 wv;
    int ch = blockIdx.x;
    if (ch < nch) {
        const float* xp = x + (size_t)((ch << 5) + lane) * 512 + w * 8;
#pragma unroll
        for (int s = 0; s < 4; ++s) {
            xv[2 * s] = *(const float4*)(xp + s * 128);
            xv[2 * s + 1] = *(const float4*)(xp + s * 128 + 4);
        }
        wv = ((const float4*)g_w)[(ch << 5) + lane];
    }

    for (; ch < nch; ch += gridDim.x) {
        const int b0 = ch << 5;
        __syncthreads();  // previous chunk's sC fully consumed
        // build c vectors from registers
        {
            const int kbase = w * 8;
#pragma unroll
            for (int j = 0; j < 8; ++j) {
                const float4 xa = xv[(j >> 2)];          // s=0 pair select below
                // gather x[s][j]: xv[2*s + (j>>2)] component (j&3)
                float xs[4];
#pragma unroll
                for (int s = 0; s < 4; ++s) {
                    const float4 v = xv[2 * s + (j >> 2)];
                    xs[s] = (j & 3) == 0 ? v.x : (j & 3) == 1 ? v.y : (j & 3) == 2 ? v.z : v.w;
                }
                (void)xa;
                const float a0 = wv.x * xs[0], a1 = wv.y * xs[1];
                const float a2 = wv.z * xs[2], a3 = wv.w * xs[3];
                sC[(kbase + j) * 32 + lane] = make_float4(a0 + a1, a0 - a1, a2 + a3, a2 - a3);
            }
        }
        __syncthreads();
        // prefetch next chunk's x/w while GEMM runs
        const int nx = ch + gridDim.x;
        if (nx < nch) {
            const float* xp = x + (size_t)((nx << 5) + lane) * 512 + w * 8;
#pragma unroll
            for (int s = 0; s < 4; ++s) {
                xv[2 * s] = *(const float4*)(xp + s * 128);
                xv[2 * s + 1] = *(const float4*)(xp + s * 128 + 4);
            }
            wv = ((const float4*)g_w)[(nx << 5) + lane];
        }

        ull accE[4] = {0, 0, 0, 0}, accO[4] = {0, 0, 0, 0};
#pragma unroll 4
        for (int k = 0; k < 128; ++k) {
            const float4 cv = sC[k * 32 + lane];
            const ull dA0 = pack_dup(cv.x), dA1 = pack_dup(cv.y);
            const ull dB0 = pack_dup(cv.z), dB1 = pack_dup(cv.w);
            const ulonglong2* m0 = (const ulonglong2*)(sM0 + k * 128 + o0);
            const ulonglong2* m1 = (const ulonglong2*)(sM1 + k * 128 + o0);
            const ulonglong2 m0a = m0[0], m0b = m0[1];
            const ulonglong2 m1a = m1[0], m1b = m1[1];
            fma2(accE[0], m0a.x, dA0); fma2(accE[1], m0a.y, dA0);
            fma2(accE[2], m0b.x, dA0); fma2(accE[3], m0b.y, dA0);
            fma2(accO[0], m0a.x, dA1); fma2(accO[1], m0a.y, dA1);
            fma2(accO[2], m0b.x, dA1); fma2(accO[3], m0b.y, dA1);
            fma2(accE[0], m1a.x, dB0); fma2(accE[1], m1a.y, dB0);
            fma2(accE[2], m1b.x, dB0); fma2(accE[3], m1b.y, dB0);
            fma2(accO[0], m1a.x, dB1); fma2(accO[1], m1a.y, dB1);
            fma2(accO[2], m1b.x, dB1); fma2(accO[3], m1b.y, dB1);
        }

        // epilogue: bias + leaky, coalesced float2 rows
        const int bg = b0 + lane;
        const int g = bg >> 9, d = bg & 511;
        float* op = out + ((size_t)(g * 128 + o0)) * 1024 + 2 * d;
#pragma unroll
        for (int p = 0; p < 4; ++p) {
            float e0 = f2lo(accE[p]) + tb[2 * p];
            float q0 = f2lo(accO[p]) + tb[2 * p];
            float e1 = f2hi(accE[p]) + tb[2 * p + 1];
            float q1 = f2hi(accO[p]) + tb[2 * p + 1];
            e0 = e0 > 0.f ? e0 : 0.01f * e0;
            q0 = q0 > 0.f ? q0 : 0.01f * q0;
            e1 = e1 > 0.f ? e1 : 0.01f * e1;
            q1 = q1 > 0.f ? q1 : 0.01f * q1;
            *(float2*)(op + (size_t)(2 * p) * 1024) = make_float2(e0, q0);
            *(float2*)(op + (size_t)(2 * p + 1) * 1024) = make_float2(e1, q1);
        }
    }
}

// ---------------- launch ----------------
extern "C" void kernel_launch(void* const* d_in, const int* in_sizes, int n_in,
                              void* d_out, int out_size) {
    const float* x = (const float*)d_in[0];
    const float* y = (const float*)d_in[1];
    const float* Wq = (const float*)d_in[2];
    const float* Wk = (const float*)d_in[3];
    const float* Wv = (const float*)d_in[4];
    const float* conv_w = (const float*)d_in[5];
    const float* conv_b = (const float*)d_in[6];
    const float* gamma = (const float*)d_in[7];
    const float* beta = (const float*)d_in[8];
    const float* mean = (const float*)d_in[9];
    const float* var = (const float*)d_in[10];
    const int B = in_sizes[0] / (4 * K);

    const size_t attn_smem = (size_t)(16384 + 8192 + 2048) * sizeof(float);  // 106496
    const size_t z_smem = (size_t)(3 * 16384) * sizeof(float);               // 196608
    cudaFuncSetAttribute(attn_kernel, cudaFuncAttributeMaxDynamicSharedMemorySize, (int)attn_smem);
    cudaFuncSetAttribute(z_kernel, cudaFuncAttributeMaxDynamicSharedMemorySize, (int)z_smem);

    setup_kernel<<<dim3(K, 3), 256>>>(Wq, Wk, Wv, conv_w, conv_b, gamma, beta, mean, var);
    attn_kernel<<<296, 256, attn_smem>>>(x, y, B);
    z_kernel<<<148, 512, z_smem>>>(x, (float*)d_out, B);
}

// round 12
// speedup vs baseline: 1.3224x; 1.3224x over previous
#include <cuda_runtime.h>
#include <cstdint>

#define K 128

typedef unsigned long long ull;

__device__ float g_A[K * K];
__device__ float g_M0[K * K];     // [k][o]
__device__ float g_M1[K * K];     // [k][o]
__device__ float g_tb[K];
__device__ float g_w[32768 * 4];

__device__ __forceinline__ ull pack_dup(float v) {
    unsigned u = __float_as_uint(v);
    ull r;
    asm("mov.b64 %0, {%1, %1};" : "=l"(r) : "r"(u));
    return r;
}
__device__ __forceinline__ void fma2(ull& acc, ull a, ull b) {
    asm("fma.rn.f32x2 %0, %1, %2, %0;" : "+l"(acc) : "l"(a), "l"(b));
}
__device__ __forceinline__ float f2lo(ull v) { return __uint_as_float((unsigned)v); }
__device__ __forceinline__ float f2hi(ull v) { return __uint_as_float((unsigned)(v >> 32)); }

// ---------------- setup ----------------
__global__ __launch_bounds__(256) void setup_kernel(
    const float* __restrict__ Wq, const float* __restrict__ Wk, const float* __restrict__ Wv,
    const float* __restrict__ conv_w, const float* __restrict__ conv_b,
    const float* __restrict__ gamma, const float* __restrict__ beta,
    const float* __restrict__ mean, const float* __restrict__ var) {
    const int m = blockIdx.y, r = blockIdx.x, t = threadIdx.x;
    const int j = t & 127, h = t >> 7;
    __shared__ float row[K];
    __shared__ float red[256];
    if (m == 0) {
        if (t < K) row[t] = Wq[t * K + r];
        __syncthreads();
        float acc = 0.f;
        const int o0 = h * 64;
#pragma unroll 8
        for (int o = 0; o < 64; ++o) acc += row[o0 + o] * Wk[(o0 + o) * K + j];
        red[t] = acc;
        __syncthreads();
        if (t < K) g_A[r * K + t] = (red[t] + red[t + 128]) * 0.08838834764831845f;
    } else {
        if (t < K) row[t] = conv_w[r * 256 + (m == 2 ? K : 0) + t];
        __syncthreads();
        float acc = 0.f;
        const int c0 = h * 64;
#pragma unroll 8
        for (int c = 0; c < 64; ++c) acc += row[c0 + c] * Wv[(c0 + c) * K + j];
        red[t] = acc;
        __syncthreads();
        if (t < K) {
            const float sc = gamma[r] * rsqrtf(var[r] + 1e-5f);
            const float val = (red[t] + red[t + 128]) * sc * 0.7071067811865476f;
            if (m == 1) {
                g_M0[t * K + r] = val;
                if (t == 0) g_tb[r] = (conv_b[r] - mean[r]) * sc + beta[r];
            } else {
                g_M1[t * K + r] = val;
            }
        }
    }
}

// ---------------- attention: chunk 32 b, 8 warps ----------------
// GEMM: warp w -> j-block w*16, lane = b. Then P->smem, dot laned by j (coalesced x).
__global__ __launch_bounds__(256, 2) void attn_kernel(const float* __restrict__ x,
                                                      const float* __restrict__ y, int B) {
    extern __shared__ float sm[];
    float* sA = sm;               // 16384
    float* sY = sA + 16384;       // [b][i] pad 129 : 32*129 = 4128
    float* sP = sY + 4128;        // [b][j] pad 132 : 32*132 = 4224
    float* sD = sP + 4224;        // 128
    const int t = threadIdx.x;
    const int lane = t & 31, w = t >> 5;

    for (int i = t; i < 4096; i += 256) ((float4*)sA)[i] = ((const float4*)g_A)[i];

    const int nch = B >> 5;
    for (int ch = blockIdx.x; ch < nch; ch += gridDim.x) {
        const int b0 = ch << 5;
        __syncthreads();
        // stage y: b = t>>3, 16 i's per thread; pad-129 rows
        {
            const int b = t >> 3, iq = t & 7;
            const float4* yp = (const float4*)(y + (size_t)(b0 + b) * K + iq * 16);
            float* dst = sY + b * 129 + iq * 16;
#pragma unroll
            for (int q = 0; q < 4; ++q) {
                const float4 v = yp[q];
                dst[q * 4 + 0] = v.x;
                dst[q * 4 + 1] = v.y;
                dst[q * 4 + 2] = v.z;
                dst[q * 4 + 3] = v.w;
            }
        }
        __syncthreads();

        // P-GEMM: acc[8] ull = 16 j for this warp, b = lane
        ull acc[8];
#pragma unroll
        for (int q = 0; q < 8; ++q) acc[q] = 0;
        {
            const float* Ab = sA + w * 16;
            const float* yr = sY + lane * 129;
#pragma unroll 4
            for (int i = 0; i < 128; ++i) {
                const ull yv = pack_dup(yr[i]);
                const ulonglong2* ap = (const ulonglong2*)(Ab + i * 128);
                const ulonglong2 a01 = ap[0];
                const ulonglong2 a23 = ap[1];
                fma2(acc[0], a01.x, yv);
                fma2(acc[1], a01.y, yv);
                fma2(acc[2], a23.x, yv);
                fma2(acc[3], a23.y, yv);
                const ulonglong2 a45 = ap[2];
                const ulonglong2 a67 = ap[3];
                fma2(acc[4], a45.x, yv);
                fma2(acc[5], a45.y, yv);
                fma2(acc[6], a67.x, yv);
                fma2(acc[7], a67.y, yv);
            }
        }
        // store P[b][j], row pad 132 (8B-aligned, conflict-light)
        {
            float* pr = sP + lane * 132 + w * 16;
#pragma unroll
            for (int q = 0; q < 8; ++q) *(ull*)(pr + 2 * q) = acc[q];
        }
        __syncthreads();

        // dot phase: warp w -> b in [w*4, w*4+4); lane = float4-idx over 128 j
        {
#pragma unroll
            for (int bb = 0; bb < 4; ++bb) {
                const int b = w * 4 + bb;
                const float4 pv = *(const float4*)(sP + b * 132 + lane * 4);
                const float4* xb = (const float4*)(x + ((size_t)(b0 + b)) * 512);
#pragma unroll
                for (int s = 0; s < 4; ++s) {
                    const float4 xv = xb[s * 32 + lane];
                    float d = xv.x * pv.x + xv.y * pv.y + xv.z * pv.z + xv.w * pv.w;
                    d += __shfl_xor_sync(0xffffffffu, d, 16);
                    d += __shfl_xor_sync(0xffffffffu, d, 8);
                    d += __shfl_xor_sync(0xffffffffu, d, 4);
                    d += __shfl_xor_sync(0xffffffffu, d, 2);
                    d += __shfl_xor_sync(0xffffffffu, d, 1);
                    if (lane == 0) sD[b * 4 + s] = d;
                }
            }
        }
        __syncthreads();

        if (t < 32) {
            const float d0 = sD[t * 4], d1 = sD[t * 4 + 1];
            const float d2 = sD[t * 4 + 2], d3 = sD[t * 4 + 3];
            const float mx = fmaxf(fmaxf(d0, d1), fmaxf(d2, d3));
            const float e0 = expf(d0 - mx), e1 = expf(d1 - mx);
            const float e2 = expf(d2 - mx), e3 = expf(d3 - mx);
            const float inv = 1.f / (e0 + e1 + e2 + e3);
            ((float4*)g_w)[b0 + t] = make_float4(e0 * inv, e1 * inv, e2 * inv, e3 * inv);
        }
    }
}

// ---------------- z kernel (unchanged from best passing version) ----------------
__global__ __launch_bounds__(512) void z_kernel(const float* __restrict__ x,
                                                float* __restrict__ out, int B) {
    extern __shared__ float sm[];
    float* sM0 = sm;
    float* sM1 = sM0 + 16384;
    float4* sC = (float4*)(sM1 + 16384);
    const int t = threadIdx.x;
    const int lane = t & 31, w = t >> 5;

    for (int i = t; i < 4096; i += 512) {
        ((float4*)sM0)[i] = ((const float4*)g_M0)[i];
        ((float4*)sM1)[i] = ((const float4*)g_M1)[i];
    }
    const int o0 = w * 8;
    float tb[8];
#pragma unroll
    for (int q = 0; q < 8; ++q) tb[q] = g_tb[o0 + q];

    const int nch = B >> 5;
    float4 xv[8];
    float4 wv;
    int ch = blockIdx.x;
    if (ch < nch) {
        const float* xp = x + (size_t)((ch << 5) + lane) * 512 + w * 8;
#pragma unroll
        for (int s = 0; s < 4; ++s) {
            xv[2 * s] = *(const float4*)(xp + s * 128);
            xv[2 * s + 1] = *(const float4*)(xp + s * 128 + 4);
        }
        wv = ((const float4*)g_w)[(ch << 5) + lane];
    }

    for (; ch < nch; ch += gridDim.x) {
        const int b0 = ch << 5;
        __syncthreads();
        {
            const int kbase = w * 8;
#pragma unroll
            for (int j = 0; j < 8; ++j) {
                float xs[4];
#pragma unroll
                for (int s = 0; s < 4; ++s) {
                    const float4 v = xv[2 * s + (j >> 2)];
                    xs[s] = (j & 3) == 0 ? v.x : (j & 3) == 1 ? v.y : (j & 3) == 2 ? v.z : v.w;
                }
                const float a0 = wv.x * xs[0], a1 = wv.y * xs[1];
                const float a2 = wv.z * xs[2], a3 = wv.w * xs[3];
                sC[(kbase + j) * 32 + lane] = make_float4(a0 + a1, a0 - a1, a2 + a3, a2 - a3);
            }
        }
        __syncthreads();
        const int nx = ch + gridDim.x;
        if (nx < nch) {
            const float* xp = x + (size_t)((nx << 5) + lane) * 512 + w * 8;
#pragma unroll
            for (int s = 0; s < 4; ++s) {
                xv[2 * s] = *(const float4*)(xp + s * 128);
                xv[2 * s + 1] = *(const float4*)(xp + s * 128 + 4);
            }
            wv = ((const float4*)g_w)[(nx << 5) + lane];
        }

        ull accE[4] = {0, 0, 0, 0}, accO[4] = {0, 0, 0, 0};
#pragma unroll 4
        for (int k = 0; k < 128; ++k) {
            const float4 cv = sC[k * 32 + lane];
            const ull dA0 = pack_dup(cv.x), dA1 = pack_dup(cv.y);
            const ull dB0 = pack_dup(cv.z), dB1 = pack_dup(cv.w);
            const ulonglong2* m0 = (const ulonglong2*)(sM0 + k * 128 + o0);
            const ulonglong2* m1 = (const ulonglong2*)(sM1 + k * 128 + o0);
            const ulonglong2 m0a = m0[0], m0b = m0[1];
            const ulonglong2 m1a = m1[0], m1b = m1[1];
            fma2(accE[0], m0a.x, dA0); fma2(accE[1], m0a.y, dA0);
            fma2(accE[2], m0b.x, dA0); fma2(accE[3], m0b.y, dA0);
            fma2(accO[0], m0a.x, dA1); fma2(accO[1], m0a.y, dA1);
            fma2(accO[2], m0b.x, dA1); fma2(accO[3], m0b.y, dA1);
            fma2(accE[0], m1a.x, dB0); fma2(accE[1], m1a.y, dB0);
            fma2(accE[2], m1b.x, dB0); fma2(accE[3], m1b.y, dB0);
            fma2(accO[0], m1a.x, dB1); fma2(accO[1], m1a.y, dB1);
            fma2(accO[2], m1b.x, dB1); fma2(accO[3], m1b.y, dB1);
        }

        const int bg = b0 + lane;
        const int g = bg >> 9, d = bg & 511;
        float* op = out + ((size_t)(g * 128 + o0)) * 1024 + 2 * d;
#pragma unroll
        for (int p = 0; p < 4; ++p) {
            float e0 = f2lo(accE[p]) + tb[2 * p];
            float q0 = f2lo(accO[p]) + tb[2 * p];
            float e1 = f2hi(accE[p]) + tb[2 * p + 1];
            float q1 = f2hi(accO[p]) + tb[2 * p + 1];
            e0 = e0 > 0.f ? e0 : 0.01f * e0;
            q0 = q0 > 0.f ? q0 : 0.01f * q0;
            e1 = e1 > 0.f ? e1 : 0.01f * e1;
            q1 = q1 > 0.f ? q1 : 0.01f * q1;
            *(float2*)(op + (size_t)(2 * p) * 1024) = make_float2(e0, q0);
            *(float2*)(op + (size_t)(2 * p + 1) * 1024) = make_float2(e1, q1);
        }
    }
}

extern "C" void kernel_launch(void* const* d_in, const int* in_sizes, int n_in,
                              void* d_out, int out_size) {
    const float* x = (const float*)d_in[0];
    const float* y = (const float*)d_in[1];
    const int B = in_sizes[0] / (4 * K);

    const size_t attn_smem = (size_t)(16384 + 4128 + 4224 + 128) * sizeof(float);
    const size_t z_smem = (size_t)(3 * 16384) * sizeof(float);
    cudaFuncSetAttribute(attn_kernel, cudaFuncAttributeMaxDynamicSharedMemorySize, (int)attn_smem);
    cudaFuncSetAttribute(z_kernel, cudaFuncAttributeMaxDynamicSharedMemorySize, (int)z_smem);

    setup_kernel<<<dim3(K, 3), 256>>>((const float*)d_in[2], (const float*)d_in[3],
                                      (const float*)d_in[4], (const float*)d_in[5],
                                      (const float*)d_in[6], (const float*)d_in[7],
                                      (const float*)d_in[8], (const float*)d_in[9],
                                      (const float*)d_in[10]);
    attn_kernel<<<296, 256, attn_smem>>>(x, y, B);
    z_kernel<<<148, 512, z_smem>>>(x, (float*)d_out, B);
}

// round 14
// speedup vs baseline: 2.1426x; 1.6202x over previous
#include <cuda_runtime.h>
#include <cuda_bf16.h>
#include <cstdint>

#define K 128

typedef unsigned long long ull;
typedef unsigned int uint;

__device__ float g_A[K * K];
__device__ float g_tb[K];
__device__ float g_w[32768 * 4];
__device__ __align__(16) __nv_bfloat16 g_Mhi[128 * 256];  // Mcat bf16 hi, [o][k]
__device__ __align__(16) __nv_bfloat16 g_Mlo[128 * 256];  // residual lo, [o][k]

// ---------------- helpers ----------------
__device__ __forceinline__ ull pack_dup(float v) {
    unsigned u = __float_as_uint(v);
    ull r;
    asm("mov.b64 %0, {%1, %1};" : "=l"(r) : "r"(u));
    return r;
}
__device__ __forceinline__ void fma2(ull& acc, ull a, ull b) {
    asm("fma.rn.f32x2 %0, %1, %2, %0;" : "+l"(acc) : "l"(a), "l"(b));
}
__device__ __forceinline__ uint pk(float lo, float hi) {
    uint r;
    asm("cvt.rn.bf16x2.f32 %0, %1, %2;" : "=r"(r) : "f"(hi), "f"(lo));
    return r;
}
__device__ __forceinline__ float blo(uint u) { return __uint_as_float(u << 16); }
__device__ __forceinline__ float bhif(uint u) { return __uint_as_float(u & 0xffff0000u); }

__device__ __forceinline__ void mma_bf16(float* d, uint a0, uint a1, uint a2, uint a3,
                                         uint b0, uint b1) {
    asm volatile(
        "mma.sync.aligned.m16n8k16.row.col.f32.bf16.bf16.f32 "
        "{%0,%1,%2,%3}, {%4,%5,%6,%7}, {%8,%9}, {%0,%1,%2,%3};"
        : "+f"(d[0]), "+f"(d[1]), "+f"(d[2]), "+f"(d[3])
        : "r"(a0), "r"(a1), "r"(a2), "r"(a3), "r"(b0), "r"(b1));
}

// ---------------- setup ----------------
__global__ __launch_bounds__(256) void setup_kernel(
    const float* __restrict__ Wq, const float* __restrict__ Wk, const float* __restrict__ Wv,
    const float* __restrict__ conv_w, const float* __restrict__ conv_b,
    const float* __restrict__ gamma, const float* __restrict__ beta,
    const float* __restrict__ mean, const float* __restrict__ var) {
    const int m = blockIdx.y, r = blockIdx.x, t = threadIdx.x;
    const int j = t & 127, h = t >> 7;
    __shared__ float row[K];
    __shared__ float red[256];
    if (m == 0) {
        if (t < K) row[t] = Wq[t * K + r];
        __syncthreads();
        float acc = 0.f;
        const int o0 = h * 64;
#pragma unroll 8
        for (int o = 0; o < 64; ++o) acc += row[o0 + o] * Wk[(o0 + o) * K + j];
        red[t] = acc;
        __syncthreads();
        if (t < K) g_A[r * K + t] = (red[t] + red[t + 128]) * 0.08838834764831845f;
    } else {
        if (t < K) row[t] = conv_w[r * 256 + (m == 2 ? K : 0) + t];
        __syncthreads();
        float acc = 0.f;
        const int c0 = h * 64;
#pragma unroll 8
        for (int c = 0; c < 64; ++c) acc += row[c0 + c] * Wv[(c0 + c) * K + j];
        red[t] = acc;
        __syncthreads();
        if (t < K) {
            const float sc = gamma[r] * rsqrtf(var[r] + 1e-5f);
            const float val = (red[t] + red[t + 128]) * sc * 0.7071067811865476f;
            const int kk = t + (m == 2 ? 128 : 0);
            const __nv_bfloat16 hb = __float2bfloat16(val);
            const float resid = val - __bfloat162float(hb);
            g_Mhi[r * 256 + kk] = hb;
            g_Mlo[r * 256 + kk] = __float2bfloat16(resid);
            if (m == 1 && t == 0) g_tb[r] = (conv_b[r] - mean[r]) * sc + beta[r];
        }
    }
}

// ---------------- attention (unchanged, passing) ----------------
__global__ __launch_bounds__(256, 2) void attn_kernel(const float* __restrict__ x,
                                                      const float* __restrict__ y, int B) {
    extern __shared__ float sm[];
    float* sA = sm;
    float* sY = sA + 16384;
    float* sP = sY + 4128;
    float* sD = sP + 4224;
    const int t = threadIdx.x;
    const int lane = t & 31, w = t >> 5;

    for (int i = t; i < 4096; i += 256) ((float4*)sA)[i] = ((const float4*)g_A)[i];

    const int nch = B >> 5;
    for (int ch = blockIdx.x; ch < nch; ch += gridDim.x) {
        const int b0 = ch << 5;
        __syncthreads();
        {
            const int b = t >> 3, iq = t & 7;
            const float4* yp = (const float4*)(y + (size_t)(b0 + b) * K + iq * 16);
            float* dst = sY + b * 129 + iq * 16;
#pragma unroll
            for (int q = 0; q < 4; ++q) {
                const float4 v = yp[q];
                dst[q * 4 + 0] = v.x; dst[q * 4 + 1] = v.y;
                dst[q * 4 + 2] = v.z; dst[q * 4 + 3] = v.w;
            }
        }
        __syncthreads();

        ull acc[8];
#pragma unroll
        for (int q = 0; q < 8; ++q) acc[q] = 0;
        {
            const float* Ab = sA + w * 16;
            const float* yr = sY + lane * 129;
#pragma unroll 4
            for (int i = 0; i < 128; ++i) {
                const ull yv = pack_dup(yr[i]);
                const ulonglong2* ap = (const ulonglong2*)(Ab + i * 128);
                const ulonglong2 a01 = ap[0];
                const ulonglong2 a23 = ap[1];
                fma2(acc[0], a01.x, yv); fma2(acc[1], a01.y, yv);
                fma2(acc[2], a23.x, yv); fma2(acc[3], a23.y, yv);
                const ulonglong2 a45 = ap[2];
                const ulonglong2 a67 = ap[3];
                fma2(acc[4], a45.x, yv); fma2(acc[5], a45.y, yv);
                fma2(acc[6], a67.x, yv); fma2(acc[7], a67.y, yv);
            }
        }
        {
            float* pr = sP + lane * 132 + w * 16;
#pragma unroll
            for (int q = 0; q < 8; ++q) *(ull*)(pr + 2 * q) = acc[q];
        }
        __syncthreads();
        {
#pragma unroll
            for (int bb = 0; bb < 4; ++bb) {
                const int b = w * 4 + bb;
                const float4 pv = *(const float4*)(sP + b * 132 + lane * 4);
                const float4* xb = (const float4*)(x + ((size_t)(b0 + b)) * 512);
#pragma unroll
                for (int s = 0; s < 4; ++s) {
                    const float4 xv = xb[s * 32 + lane];
                    float d = xv.x * pv.x + xv.y * pv.y + xv.z * pv.z + xv.w * pv.w;
                    d += __shfl_xor_sync(0xffffffffu, d, 16);
                    d += __shfl_xor_sync(0xffffffffu, d, 8);
                    d += __shfl_xor_sync(0xffffffffu, d, 4);
                    d += __shfl_xor_sync(0xffffffffu, d, 2);
                    d += __shfl_xor_sync(0xffffffffu, d, 1);
                    if (lane == 0) sD[b * 4 + s] = d;
                }
            }
        }
        __syncthreads();
        if (t < 32) {
            const float d0 = sD[t * 4], d1 = sD[t * 4 + 1];
            const float d2 = sD[t * 4 + 2], d3 = sD[t * 4 + 3];
            const float mx = fmaxf(fmaxf(d0, d1), fmaxf(d2, d3));
            const float e0 = expf(d0 - mx), e1 = expf(d1 - mx);
            const float e2 = expf(d2 - mx), e3 = expf(d3 - mx);
            const float inv = 1.f / (e0 + e1 + e2 + e3);
            ((float4*)g_w)[b0 + t] = make_float4(e0 * inv, e1 * inv, e2 * inv, e3 * inv);
        }
    }
}

// ---------------- z kernel: mma.sync bf16x3 ----------------
// smem bytes: Ah [128][264]bf16 = 67584 | Al 67584 | Bh [64][264]bf16 = 33792 | Bl 33792
#define ROWB 528  // bytes per padded row (264 bf16); 528 % 128 = 16 -> conflict-free
#define SM_AH 0
#define SM_AL 67584
#define SM_BH 135168
#define SM_BL 168960
#define SM_TOT 202752

__global__ __launch_bounds__(512, 1) void z_kernel(const float* __restrict__ x,
                                                   float* __restrict__ out, int B) {
    extern __shared__ char smc[];
    const int t = threadIdx.x;
    const int lane = t & 31, w = t >> 5;

    // load A hi/lo into padded smem
    for (int i = t; i < 4096; i += 512) {
        const int row = i >> 5, c = i & 31;
        *(uint4*)(smc + SM_AH + row * ROWB + c * 16) = ((const uint4*)g_Mhi)[i];
        *(uint4*)(smc + SM_AL + row * ROWB + c * 16) = ((const uint4*)g_Mlo)[i];
    }

    const int o_base = (w & 7) * 16;
    const int nhalf = w >> 3;
    const int r4 = lane >> 2, cq = lane & 3;
    const float tb0 = g_tb[o_base + r4];
    const float tb1 = g_tb[o_base + r4 + 8];

    const char* Ahp = smc + SM_AH + (o_base + r4) * ROWB + cq * 4;
    const char* Alp = smc + SM_AL + (o_base + r4) * ROWB + cq * 4;
    const char* Bhp = smc + SM_BH + (nhalf * 32 + r4) * ROWB + cq * 4;
    const char* Blp = smc + SM_BL + (nhalf * 32 + r4) * ROWB + cq * 4;

    const int nch = B >> 5;
    for (int ch = blockIdx.x; ch < nch; ch += gridDim.x) {
        const int b0 = ch << 5;
        __syncthreads();  // prior chunk's B fully consumed
        // ---- build B tile: warp handles b = w and b = w+16, lanes span k ----
#pragma unroll
        for (int q = 0; q < 2; ++q) {
            const int b = w + 16 * q;
            const int half = lane >> 4, ko = lane & 15;
            const float2 ws = *(const float2*)(g_w + (size_t)(b0 + b) * 4 + half * 2);
            const float* xp = x + (size_t)(b0 + b) * 512 + half * 256 + ko * 8;
            const float4 xa = *(const float4*)xp;
            const float4 xb2 = *(const float4*)(xp + 4);
            const float4 ya = *(const float4*)(xp + 128);
            const float4 yb = *(const float4*)(xp + 132);
            float vp[8], vm[8];
            const float* xs = (const float*)&xa;
            const float* ys = (const float*)&ya;
#pragma unroll
            for (int jj = 0; jj < 4; ++jj) {
                const float a0 = ws.x * xs[jj], a1 = ws.y * ys[jj];
                vp[jj] = a0 + a1; vm[jj] = a0 - a1;
            }
            const float* xs2 = (const float*)&xb2;
            const float* ys2 = (const float*)&yb;
#pragma unroll
            for (int jj = 0; jj < 4; ++jj) {
                const float a0 = ws.x * xs2[jj], a1 = ws.y * ys2[jj];
                vp[4 + jj] = a0 + a1; vm[4 + jj] = a0 - a1;
            }
            uint hp[4], hm[4], lp[4], lm[4];
#pragma unroll
            for (int jj = 0; jj < 4; ++jj) {
                hp[jj] = pk(vp[2 * jj], vp[2 * jj + 1]);
                lp[jj] = pk(vp[2 * jj] - blo(hp[jj]), vp[2 * jj + 1] - bhif(hp[jj]));
                hm[jj] = pk(vm[2 * jj], vm[2 * jj + 1]);
                lm[jj] = pk(vm[2 * jj] - blo(hm[jj]), vm[2 * jj + 1] - bhif(hm[jj]));
            }
            const int coff = (half * 128 + ko * 8) * 2;  // byte offset along k
            char* rp = smc + SM_BH + (2 * b) * ROWB + coff;
            char* rm = rp + ROWB;
            *(uint4*)rp = make_uint4(hp[0], hp[1], hp[2], hp[3]);
            *(uint4*)rm = make_uint4(hm[0], hm[1], hm[2], hm[3]);
            char* rp2 = smc + SM_BL + (2 * b) * ROWB + coff;
            *(uint4*)rp2 = make_uint4(lp[0], lp[1], lp[2], lp[3]);
            *(uint4*)(rp2 + ROWB) = make_uint4(lm[0], lm[1], lm[2], lm[3]);
        }
        __syncthreads();

        // ---- MMA: warp = (m-tile o_base, n-half); 16 k-steps x 4 n-tiles x 3 passes ----
        float d0[4] = {0, 0, 0, 0}, d1[4] = {0, 0, 0, 0};
        float d2[4] = {0, 0, 0, 0}, d3[4] = {0, 0, 0, 0};
#pragma unroll 4
        for (int ki = 0; ki < 16; ++ki) {
            const int off = ki * 32;
            const uint ah0 = *(const uint*)(Ahp + off);
            const uint ah1 = *(const uint*)(Ahp + 8 * ROWB + off);
            const uint ah2 = *(const uint*)(Ahp + off + 16);
            const uint ah3 = *(const uint*)(Ahp + 8 * ROWB + off + 16);
            const uint al0 = *(const uint*)(Alp + off);
            const uint al1 = *(const uint*)(Alp + 8 * ROWB + off);
            const uint al2 = *(const uint*)(Alp + off + 16);
            const uint al3 = *(const uint*)(Alp + 8 * ROWB + off + 16);
#pragma unroll
            for (int ni = 0; ni < 4; ++ni) {
                float* dd = ni == 0 ? d0 : ni == 1 ? d1 : ni == 2 ? d2 : d3;
                const uint bh0 = *(const uint*)(Bhp + ni * 8 * ROWB + off);
                const uint bh1 = *(const uint*)(Bhp + ni * 8 * ROWB + off + 16);
                const uint bl0 = *(const uint*)(Blp + ni * 8 * ROWB + off);
                const uint bl1 = *(const uint*)(Blp + ni * 8 * ROWB + off + 16);
                mma_bf16(dd, ah0, ah1, ah2, ah3, bh0, bh1);
                mma_bf16(dd, ah0, ah1, ah2, ah3, bl0, bl1);
                mma_bf16(dd, al0, al1, al2, al3, bh0, bh1);
            }
        }

        // ---- epilogue ----
        const int g = b0 >> 9, dbase = b0 & 511;
#pragma unroll
        for (int ni = 0; ni < 4; ++ni) {
            const float* dd = ni == 0 ? d0 : ni == 1 ? d1 : ni == 2 ? d2 : d3;
            const int b = (nhalf * 4 + ni) * 4 + cq;  // 0..31
            float* op = out + ((size_t)(g * 128 + o_base + r4)) * 1024 + 2 * (dbase + b);
            float e0 = dd[0] + tb0, e1 = dd[1] + tb0;
            float e2 = dd[2] + tb1, e3 = dd[3] + tb1;
            e0 = e0 > 0.f ? e0 : 0.01f * e0;
            e1 = e1 > 0.f ? e1 : 0.01f * e1;
            e2 = e2 > 0.f ? e2 : 0.01f * e2;
            e3 = e3 > 0.f ? e3 : 0.01f * e3;
            *(float2*)op = make_float2(e0, e1);
            *(float2*)(op + 8 * 1024) = make_float2(e2, e3);
        }
    }
}

extern "C" void kernel_launch(void* const* d_in, const int* in_sizes, int n_in,
                              void* d_out, int out_size) {
    const float* x = (const float*)d_in[0];
    const float* y = (const float*)d_in[1];
    const int B = in_sizes[0] / (4 * K);

    const size_t attn_smem = (size_t)(16384 + 4128 + 4224 + 128) * sizeof(float);
    cudaFuncSetAttribute(attn_kernel, cudaFuncAttributeMaxDynamicSharedMemorySize, (int)attn_smem);
    cudaFuncSetAttribute(z_kernel, cudaFuncAttributeMaxDynamicSharedMemorySize, SM_TOT);

    setup_kernel<<<dim3(K, 3), 256>>>((const float*)d_in[2], (const float*)d_in[3],
                                      (const float*)d_in[4], (const float*)d_in[5],
                                      (const float*)d_in[6], (const float*)d_in[7],
                                      (const float*)d_in[8], (const float*)d_in[9],
                                      (const float*)d_in[10]);
    attn_kernel<<<296, 256, attn_smem>>>(x, y, B);
    z_kernel<<<148, 512, SM_TOT>>>(x, (float*)d_out, B);
}

// round 15
// speedup vs baseline: 2.5309x; 1.1812x over previous
#include <cuda_runtime.h>
#include <cuda_bf16.h>
#include <cstdint>

#define K 128

typedef unsigned long long ull;
typedef unsigned int uint;

__device__ float g_tb[K];
__device__ float g_w[32768 * 4];
__device__ __align__(16) __nv_bfloat16 g_Mhi[128 * 256];  // Mcat bf16 hi, [o][k]
__device__ __align__(16) __nv_bfloat16 g_Mlo[128 * 256];  // residual lo, [o][k]
__device__ __align__(16) __nv_bfloat16 g_ATh[128 * 128];  // A^T bf16 hi, [j][i]
__device__ __align__(16) __nv_bfloat16 g_ATl[128 * 128];  // A^T residual, [j][i]

// ---------------- helpers ----------------
__device__ __forceinline__ uint pk(float lo, float hi) {
    uint r;
    asm("cvt.rn.bf16x2.f32 %0, %1, %2;" : "=r"(r) : "f"(hi), "f"(lo));
    return r;
}
__device__ __forceinline__ float blo(uint u) { return __uint_as_float(u << 16); }
__device__ __forceinline__ float bhif(uint u) { return __uint_as_float(u & 0xffff0000u); }

__device__ __forceinline__ void mma_bf16(float* d, uint a0, uint a1, uint a2, uint a3,
                                         uint b0, uint b1) {
    asm volatile(
        "mma.sync.aligned.m16n8k16.row.col.f32.bf16.bf16.f32 "
        "{%0,%1,%2,%3}, {%4,%5,%6,%7}, {%8,%9}, {%0,%1,%2,%3};"
        : "+f"(d[0]), "+f"(d[1]), "+f"(d[2]), "+f"(d[3])
        : "r"(a0), "r"(a1), "r"(a2), "r"(a3), "r"(b0), "r"(b1));
}

// ---------------- setup ----------------
__global__ __launch_bounds__(256) void setup_kernel(
    const float* __restrict__ Wq, const float* __restrict__ Wk, const float* __restrict__ Wv,
    const float* __restrict__ conv_w, const float* __restrict__ conv_b,
    const float* __restrict__ gamma, const float* __restrict__ beta,
    const float* __restrict__ mean, const float* __restrict__ var) {
    const int m = blockIdx.y, r = blockIdx.x, t = threadIdx.x;
    const int j = t & 127, h = t >> 7;
    __shared__ float row[K];
    __shared__ float red[256];
    if (m == 0) {
        if (t < K) row[t] = Wq[t * K + r];
        __syncthreads();
        float acc = 0.f;
        const int o0 = h * 64;
#pragma unroll 8
        for (int o = 0; o < 64; ++o) acc += row[o0 + o] * Wk[(o0 + o) * K + j];
        red[t] = acc;
        __syncthreads();
        if (t < K) {
            const float val = (red[t] + red[t + 128]) * 0.08838834764831845f;  // A[r][t]
            const __nv_bfloat16 hb = __float2bfloat16(val);
            g_ATh[t * 128 + r] = hb;  // transposed [j][i]
            g_ATl[t * 128 + r] = __float2bfloat16(val - __bfloat162float(hb));
        }
    } else {
        if (t < K) row[t] = conv_w[r * 256 + (m == 2 ? K : 0) + t];
        __syncthreads();
        float acc = 0.f;
        const int c0 = h * 64;
#pragma unroll 8
        for (int c = 0; c < 64; ++c) acc += row[c0 + c] * Wv[(c0 + c) * K + j];
        red[t] = acc;
        __syncthreads();
        if (t < K) {
            const float sc = gamma[r] * rsqrtf(var[r] + 1e-5f);
            const float val = (red[t] + red[t + 128]) * sc * 0.7071067811865476f;
            const int kk = t + (m == 2 ? 128 : 0);
            const __nv_bfloat16 hb = __float2bfloat16(val);
            g_Mhi[r * 256 + kk] = hb;
            g_Mlo[r * 256 + kk] = __float2bfloat16(val - __bfloat162float(hb));
            if (m == 1 && t == 0) g_tb[r] = (conv_b[r] - mean[r]) * sc + beta[r];
        }
    }
}

// ---------------- attention: HMMA bf16x3 P-GEMM + dot + softmax ----------------
// chunk = 64 b. 16 warps: warp = (mt = w&3 -> m16 rows, ng = w>>2 -> 4 n8-tiles).
// smem bytes: ATh 67584 | ATl 67584 | Yh 33792 (aliased by P) | Yl 33792 | D 1024
#define AROWB 528
#define ATN_ATH 0
#define ATN_ATL 67584
#define ATN_Y 135168
#define ATN_YL 168960
#define ATN_D 202752
#define ATN_TOT 203776

__global__ __launch_bounds__(512, 1) void attn_kernel(const float* __restrict__ x,
                                                      const float* __restrict__ y, int B) {
    extern __shared__ char smc[];
    const int t = threadIdx.x;
    const int lane = t & 31, w = t >> 5;

    for (int i = t; i < 2048; i += 512) {
        const int r = i >> 4, c = i & 15;
        *(uint4*)(smc + ATN_ATH + r * AROWB + c * 16) = ((const uint4*)g_ATh)[i];
        *(uint4*)(smc + ATN_ATL + r * AROWB + c * 16) = ((const uint4*)g_ATl)[i];
    }
    const int mt = w & 3, ng = w >> 2;
    const int r4 = lane >> 2, cq = lane & 3;
    const char* Yhp = smc + ATN_Y + (mt * 16 + r4) * AROWB + cq * 4;
    const char* Ylp = smc + ATN_YL + (mt * 16 + r4) * AROWB + cq * 4;
    const char* Bhp = smc + ATN_ATH + (ng * 32 + r4) * AROWB + cq * 4;
    const char* Blp = smc + ATN_ATL + (ng * 32 + r4) * AROWB + cq * 4;
    float* sP = (float*)(smc + ATN_Y);
    float* sD = (float*)(smc + ATN_D);

    const int nch = B >> 6;
    for (int ch = blockIdx.x; ch < nch; ch += gridDim.x) {
        const int b0 = ch << 6;
        __syncthreads();  // prior sP/sD consumed
        // build Y hi/lo: thread -> (b = t>>3, 16 i's)
        {
            const int b = t >> 3, iq = t & 7;
            const float4* yp = (const float4*)(y + (size_t)(b0 + b) * 128 + iq * 16);
            uint hh[8], ll[8];
#pragma unroll
            for (int q = 0; q < 4; ++q) {
                const float4 v = yp[q];
                const uint h0 = pk(v.x, v.y);
                const uint h1 = pk(v.z, v.w);
                hh[2 * q] = h0;
                hh[2 * q + 1] = h1;
                ll[2 * q] = pk(v.x - blo(h0), v.y - bhif(h0));
                ll[2 * q + 1] = pk(v.z - blo(h1), v.w - bhif(h1));
            }
            char* dh = smc + ATN_Y + b * AROWB + iq * 32;
            char* dl = smc + ATN_YL + b * AROWB + iq * 32;
            *(uint4*)dh = make_uint4(hh[0], hh[1], hh[2], hh[3]);
            *(uint4*)(dh + 16) = make_uint4(hh[4], hh[5], hh[6], hh[7]);
            *(uint4*)dl = make_uint4(ll[0], ll[1], ll[2], ll[3]);
            *(uint4*)(dl + 16) = make_uint4(ll[4], ll[5], ll[6], ll[7]);
        }
        __syncthreads();

        // P-GEMM: 8 k-steps x 4 n-tiles x 3 passes
        float d0[4] = {0, 0, 0, 0}, d1[4] = {0, 0, 0, 0};
        float d2[4] = {0, 0, 0, 0}, d3[4] = {0, 0, 0, 0};
#pragma unroll
        for (int ki = 0; ki < 8; ++ki) {
            const int off = ki * 32;
            const uint ah0 = *(const uint*)(Yhp + off);
            const uint ah1 = *(const uint*)(Yhp + 8 * AROWB + off);
            const uint ah2 = *(const uint*)(Yhp + off + 16);
            const uint ah3 = *(const uint*)(Yhp + 8 * AROWB + off + 16);
            const uint al0 = *(const uint*)(Ylp + off);
            const uint al1 = *(const uint*)(Ylp + 8 * AROWB + off);
            const uint al2 = *(const uint*)(Ylp + off + 16);
            const uint al3 = *(const uint*)(Ylp + 8 * AROWB + off + 16);
#pragma unroll
            for (int ni = 0; ni < 4; ++ni) {
                float* dd = ni == 0 ? d0 : ni == 1 ? d1 : ni == 2 ? d2 : d3;
                const uint bh0 = *(const uint*)(Bhp + ni * 8 * AROWB + off);
                const uint bh1 = *(const uint*)(Bhp + ni * 8 * AROWB + off + 16);
                const uint bl0 = *(const uint*)(Blp + ni * 8 * AROWB + off);
                const uint bl1 = *(const uint*)(Blp + ni * 8 * AROWB + off + 16);
                mma_bf16(dd, ah0, ah1, ah2, ah3, bh0, bh1);
                mma_bf16(dd, ah0, ah1, ah2, ah3, bl0, bl1);
                mma_bf16(dd, al0, al1, al2, al3, bh0, bh1);
            }
        }
        __syncthreads();  // all Yh reads done; sP aliases Yh

        // store P fragments: row pad 132 floats
#pragma unroll
        for (int ni = 0; ni < 4; ++ni) {
            const float* dd = ni == 0 ? d0 : ni == 1 ? d1 : ni == 2 ? d2 : d3;
            const int r = mt * 16 + r4;
            const int c = ng * 32 + ni * 8 + cq * 2;
            *(float2*)(sP + r * 132 + c) = make_float2(dd[0], dd[1]);
            *(float2*)(sP + (r + 8) * 132 + c) = make_float2(dd[2], dd[3]);
        }
        __syncthreads();

        // dot: warp w -> b in [w*4, w*4+4), lane = float4 idx over 128 j
#pragma unroll
        for (int bb = 0; bb < 4; ++bb) {
            const int b = w * 4 + bb;
            const float4 pv = *(const float4*)(sP + b * 132 + lane * 4);
            const float4* xb = (const float4*)(x + (size_t)(b0 + b) * 512);
#pragma unroll
            for (int s = 0; s < 4; ++s) {
                const float4 xv = xb[s * 32 + lane];
                float d = xv.x * pv.x + xv.y * pv.y + xv.z * pv.z + xv.w * pv.w;
                d += __shfl_xor_sync(0xffffffffu, d, 16);
                d += __shfl_xor_sync(0xffffffffu, d, 8);
                d += __shfl_xor_sync(0xffffffffu, d, 4);
                d += __shfl_xor_sync(0xffffffffu, d, 2);
                d += __shfl_xor_sync(0xffffffffu, d, 1);
                if (lane == 0) sD[b * 4 + s] = d;
            }
        }
        __syncthreads();
        if (t < 64) {
            const float d0s = sD[t * 4], d1s = sD[t * 4 + 1];
            const float d2s = sD[t * 4 + 2], d3s = sD[t * 4 + 3];
            const float mx = fmaxf(fmaxf(d0s, d1s), fmaxf(d2s, d3s));
            const float e0 = expf(d0s - mx), e1 = expf(d1s - mx);
            const float e2 = expf(d2s - mx), e3 = expf(d3s - mx);
            const float inv = 1.f / (e0 + e1 + e2 + e3);
            ((float4*)g_w)[b0 + t] = make_float4(e0 * inv, e1 * inv, e2 * inv, e3 * inv);
        }
    }
}

// ---------------- z kernel: mma.sync bf16x3 (unchanged, passing) ----------------
#define ROWB 528
#define SM_AH 0
#define SM_AL 67584
#define SM_BH 135168
#define SM_BL 168960
#define SM_TOT 202752

__global__ __launch_bounds__(512, 1) void z_kernel(const float* __restrict__ x,
                                                   float* __restrict__ out, int B) {
    extern __shared__ char smc[];
    const int t = threadIdx.x;
    const int lane = t & 31, w = t >> 5;

    for (int i = t; i < 4096; i += 512) {
        const int row = i >> 5, c = i & 31;
        *(uint4*)(smc + SM_AH + row * ROWB + c * 16) = ((const uint4*)g_Mhi)[i];
        *(uint4*)(smc + SM_AL + row * ROWB + c * 16) = ((const uint4*)g_Mlo)[i];
    }

    const int o_base = (w & 7) * 16;
    const int nhalf = w >> 3;
    const int r4 = lane >> 2, cq = lane & 3;
    const float tb0 = g_tb[o_base + r4];
    const float tb1 = g_tb[o_base + r4 + 8];

    const char* Ahp = smc + SM_AH + (o_base + r4) * ROWB + cq * 4;
    const char* Alp = smc + SM_AL + (o_base + r4) * ROWB + cq * 4;
    const char* Bhp = smc + SM_BH + (nhalf * 32 + r4) * ROWB + cq * 4;
    const char* Blp = smc + SM_BL + (nhalf * 32 + r4) * ROWB + cq * 4;

    const int nch = B >> 5;
    for (int ch = blockIdx.x; ch < nch; ch += gridDim.x) {
        const int b0 = ch << 5;
        __syncthreads();
#pragma unroll
        for (int q = 0; q < 2; ++q) {
            const int b = w + 16 * q;
            const int half = lane >> 4, ko = lane & 15;
            const float2 ws = *(const float2*)(g_w + (size_t)(b0 + b) * 4 + half * 2);
            const float* xp = x + (size_t)(b0 + b) * 512 + half * 256 + ko * 8;
            const float4 xa = *(const float4*)xp;
            const float4 xb2 = *(const float4*)(xp + 4);
            const float4 ya = *(const float4*)(xp + 128);
            const float4 yb = *(const float4*)(xp + 132);
            float vp[8], vm[8];
            const float* xs = (const float*)&xa;
            const float* ys = (const float*)&ya;
#pragma unroll
            for (int jj = 0; jj < 4; ++jj) {
                const float a0 = ws.x * xs[jj], a1 = ws.y * ys[jj];
                vp[jj] = a0 + a1;
                vm[jj] = a0 - a1;
            }
            const float* xs2 = (const float*)&xb2;
            const float* ys2 = (const float*)&yb;
#pragma unroll
            for (int jj = 0; jj < 4; ++jj) {
                const float a0 = ws.x * xs2[jj], a1 = ws.y * ys2[jj];
                vp[4 + jj] = a0 + a1;
                vm[4 + jj] = a0 - a1;
            }
            uint hp[4], hm[4], lp[4], lm[4];
#pragma unroll
            for (int jj = 0; jj < 4; ++jj) {
                hp[jj] = pk(vp[2 * jj], vp[2 * jj + 1]);
                lp[jj] = pk(vp[2 * jj] - blo(hp[jj]), vp[2 * jj + 1] - bhif(hp[jj]));
                hm[jj] = pk(vm[2 * jj], vm[2 * jj + 1]);
                lm[jj] = pk(vm[2 * jj] - blo(hm[jj]), vm[2 * jj + 1] - bhif(hm[jj]));
            }
            const int coff = (half * 128 + ko * 8) * 2;
            char* rp = smc + SM_BH + (2 * b) * ROWB + coff;
            *(uint4*)rp = make_uint4(hp[0], hp[1], hp[2], hp[3]);
            *(uint4*)(rp + ROWB) = make_uint4(hm[0], hm[1], hm[2], hm[3]);
            char* rp2 = smc + SM_BL + (2 * b) * ROWB + coff;
            *(uint4*)rp2 = make_uint4(lp[0], lp[1], lp[2], lp[3]);
            *(uint4*)(rp2 + ROWB) = make_uint4(lm[0], lm[1], lm[2], lm[3]);
        }
        __syncthreads();

        float d0[4] = {0, 0, 0, 0}, d1[4] = {0, 0, 0, 0};
        float d2[4] = {0, 0, 0, 0}, d3[4] = {0, 0, 0, 0};
#pragma unroll 4
        for (int ki = 0; ki < 16; ++ki) {
            const int off = ki * 32;
            const uint ah0 = *(const uint*)(Ahp + off);
            const uint ah1 = *(const uint*)(Ahp + 8 * ROWB + off);
            const uint ah2 = *(const uint*)(Ahp + off + 16);
            const uint ah3 = *(const uint*)(Ahp + 8 * ROWB + off + 16);
            const uint al0 = *(const uint*)(Alp + off);
            const uint al1 = *(const uint*)(Alp + 8 * ROWB + off);
            const uint al2 = *(const uint*)(Alp + off + 16);
            const uint al3 = *(const uint*)(Alp + 8 * ROWB + off + 16);
#pragma unroll
            for (int ni = 0; ni < 4; ++ni) {
                float* dd = ni == 0 ? d0 : ni == 1 ? d1 : ni == 2 ? d2 : d3;
                const uint bh0 = *(const uint*)(Bhp + ni * 8 * ROWB + off);
                const uint bh1 = *(const uint*)(Bhp + ni * 8 * ROWB + off + 16);
                const uint bl0 = *(const uint*)(Blp + ni * 8 * ROWB + off);
                const uint bl1 = *(const uint*)(Blp + ni * 8 * ROWB + off + 16);
                mma_bf16(dd, ah0, ah1, ah2, ah3, bh0, bh1);
                mma_bf16(dd, ah0, ah1, ah2, ah3, bl0, bl1);
                mma_bf16(dd, al0, al1, al2, al3, bh0, bh1);
            }
        }

        const int g = b0 >> 9, dbase = b0 & 511;
#pragma unroll
        for (int ni = 0; ni < 4; ++ni) {
            const float* dd = ni == 0 ? d0 : ni == 1 ? d1 : ni == 2 ? d2 : d3;
            const int b = (nhalf * 4 + ni) * 4 + cq;
            float* op = out + ((size_t)(g * 128 + o_base + r4)) * 1024 + 2 * (dbase + b);
            float e0 = dd[0] + tb0, e1 = dd[1] + tb0;
            float e2 = dd[2] + tb1, e3 = dd[3] + tb1;
            e0 = e0 > 0.f ? e0 : 0.01f * e0;
            e1 = e1 > 0.f ? e1 : 0.01f * e1;
            e2 = e2 > 0.f ? e2 : 0.01f * e2;
            e3 = e3 > 0.f ? e3 : 0.01f * e3;
            *(float2*)op = make_float2(e0, e1);
            *(float2*)(op + 8 * 1024) = make_float2(e2, e3);
        }
    }
}

extern "C" void kernel_launch(void* const* d_in, const int* in_sizes, int n_in,
                              void* d_out, int out_size) {
    const float* x = (const float*)d_in[0];
    const float* y = (const float*)d_in[1];
    const int B = in_sizes[0] / (4 * K);

    cudaFuncSetAttribute(attn_kernel, cudaFuncAttributeMaxDynamicSharedMemorySize, ATN_TOT);
    cudaFuncSetAttribute(z_kernel, cudaFuncAttributeMaxDynamicSharedMemorySize, SM_TOT);

    setup_kernel<<<dim3(K, 3), 256>>>((const float*)d_in[2], (const float*)d_in[3],
                                      (const float*)d_in[4], (const float*)d_in[5],
                                      (const float*)d_in[6], (const float*)d_in[7],
                                      (const float*)d_in[8], (const float*)d_in[9],
                                      (const float*)d_in[10]);
    attn_kernel<<<148, 512, ATN_TOT>>>(x, y, B);
    z_kernel<<<148, 512, SM_TOT>>>(x, (float*)d_out, B);
}

// round 16
// speedup vs baseline: 2.8694x; 1.1338x over previous
#include <cuda_runtime.h>
#include <cuda_bf16.h>
#include <cuda_fp16.h>
#include <cstdint>

#define K 128

typedef unsigned long long ull;
typedef unsigned int uint;

__device__ float g_tb[K];
__device__ float g_w[32768 * 4];
__device__ __align__(16) __half g_Mh[128 * 256];          // Mcat fp16, [o][k]
__device__ __align__(16) __nv_bfloat16 g_ATh[128 * 128];  // A^T bf16 hi, [j][i]
__device__ __align__(16) __nv_bfloat16 g_ATl[128 * 128];  // A^T residual, [j][i]

// ---------------- helpers ----------------
__device__ __forceinline__ uint pk(float lo, float hi) {  // bf16x2
    uint r;
    asm("cvt.rn.bf16x2.f32 %0, %1, %2;" : "=r"(r) : "f"(hi), "f"(lo));
    return r;
}
__device__ __forceinline__ float blo(uint u) { return __uint_as_float(u << 16); }
__device__ __forceinline__ float bhif(uint u) { return __uint_as_float(u & 0xffff0000u); }

__device__ __forceinline__ uint pkh(float lo, float hi) {  // f16x2
    uint r;
    asm("cvt.rn.f16x2.f32 %0, %1, %2;" : "=r"(r) : "f"(hi), "f"(lo));
    return r;
}
__device__ __forceinline__ float hlo(uint u) {
    return __half2float(__ushort_as_half((unsigned short)(u & 0xffffu)));
}
__device__ __forceinline__ float hhi(uint u) {
    return __half2float(__ushort_as_half((unsigned short)(u >> 16)));
}

__device__ __forceinline__ void mma_bf16(float* d, uint a0, uint a1, uint a2, uint a3,
                                         uint b0, uint b1) {
    asm volatile(
        "mma.sync.aligned.m16n8k16.row.col.f32.bf16.bf16.f32 "
        "{%0,%1,%2,%3}, {%4,%5,%6,%7}, {%8,%9}, {%0,%1,%2,%3};"
        : "+f"(d[0]), "+f"(d[1]), "+f"(d[2]), "+f"(d[3])
        : "r"(a0), "r"(a1), "r"(a2), "r"(a3), "r"(b0), "r"(b1));
}
__device__ __forceinline__ void mma_f16(float* d, uint a0, uint a1, uint a2, uint a3,
                                        uint b0, uint b1) {
    asm volatile(
        "mma.sync.aligned.m16n8k16.row.col.f32.f16.f16.f32 "
        "{%0,%1,%2,%3}, {%4,%5,%6,%7}, {%8,%9}, {%0,%1,%2,%3};"
        : "+f"(d[0]), "+f"(d[1]), "+f"(d[2]), "+f"(d[3])
        : "r"(a0), "r"(a1), "r"(a2), "r"(a3), "r"(b0), "r"(b1));
}

// ---------------- setup: ILP version ----------------
__global__ __launch_bounds__(256) void setup_kernel(
    const float* __restrict__ Wq, const float* __restrict__ Wk, const float* __restrict__ Wv,
    const float* __restrict__ conv_w, const float* __restrict__ conv_b,
    const float* __restrict__ gamma, const float* __restrict__ beta,
    const float* __restrict__ mean, const float* __restrict__ var) {
    const int m = blockIdx.y, r = blockIdx.x, t = threadIdx.x;
    const int jg = t & 31, h = t >> 5;
    __shared__ float row[K];
    __shared__ float4 red[8][32];
    if (t < K) row[t] = (m == 0) ? Wq[t * K + r] : conv_w[r * 256 + (m == 2 ? K : 0) + t];
    __syncthreads();
    const float4* W4 = (const float4*)((m == 0) ? Wk : Wv);
    float4 acc = make_float4(0.f, 0.f, 0.f, 0.f);
    const int o0 = h * 16;
#pragma unroll
    for (int o = 0; o < 16; ++o) {
        const float rv = row[o0 + o];
        const float4 wv = W4[(o0 + o) * 32 + jg];
        acc.x += rv * wv.x;
        acc.y += rv * wv.y;
        acc.z += rv * wv.z;
        acc.w += rv * wv.w;
    }
    red[h][jg] = acc;
    __syncthreads();
    if (t < 32) {
        float4 s = red[0][t];
#pragma unroll
        for (int q = 1; q < 8; ++q) {
            const float4 v = red[q][t];
            s.x += v.x;
            s.y += v.y;
            s.z += v.z;
            s.w += v.w;
        }
        float vals[4] = {s.x, s.y, s.z, s.w};
        if (m == 0) {
#pragma unroll
            for (int q = 0; q < 4; ++q) {
                const int j = t * 4 + q;
                const float val = vals[q] * 0.08838834764831845f;
                const __nv_bfloat16 hb = __float2bfloat16(val);
                g_ATh[j * 128 + r] = hb;
                g_ATl[j * 128 + r] = __float2bfloat16(val - __bfloat162float(hb));
            }
        } else {
            const float sc = gamma[r] * rsqrtf(var[r] + 1e-5f);
#pragma unroll
            for (int q = 0; q < 4; ++q) {
                const int kk = t * 4 + q + (m == 2 ? K : 0);
                g_Mh[r * 256 + kk] = __float2half_rn(vals[q] * sc * 0.7071067811865476f);
            }
            if (m == 1 && t == 0) g_tb[r] = (conv_b[r] - mean[r]) * sc + beta[r];
        }
    }
}

// ---------------- attention: HMMA bf16x3 (unchanged, passing) ----------------
#define AROWB 528
#define ATN_ATH 0
#define ATN_ATL 67584
#define ATN_Y 135168
#define ATN_YL 168960
#define ATN_D 202752
#define ATN_TOT 203776

__global__ __launch_bounds__(512, 1) void attn_kernel(const float* __restrict__ x,
                                                      const float* __restrict__ y, int B) {
    extern __shared__ char smc[];
    const int t = threadIdx.x;
    const int lane = t & 31, w = t >> 5;

    for (int i = t; i < 2048; i += 512) {
        const int r = i >> 4, c = i & 15;
        *(uint4*)(smc + ATN_ATH + r * AROWB + c * 16) = ((const uint4*)g_ATh)[i];
        *(uint4*)(smc + ATN_ATL + r * AROWB + c * 16) = ((const uint4*)g_ATl)[i];
    }
    const int mt = w & 3, ng = w >> 2;
    const int r4 = lane >> 2, cq = lane & 3;
    const char* Yhp = smc + ATN_Y + (mt * 16 + r4) * AROWB + cq * 4;
    const char* Ylp = smc + ATN_YL + (mt * 16 + r4) * AROWB + cq * 4;
    const char* Bhp = smc + ATN_ATH + (ng * 32 + r4) * AROWB + cq * 4;
    const char* Blp = smc + ATN_ATL + (ng * 32 + r4) * AROWB + cq * 4;
    float* sP = (float*)(smc + ATN_Y);
    float* sD = (float*)(smc + ATN_D);

    const int nch = B >> 6;
    for (int ch = blockIdx.x; ch < nch; ch += gridDim.x) {
        const int b0 = ch << 6;
        __syncthreads();
        {
            const int b = t >> 3, iq = t & 7;
            const float4* yp = (const float4*)(y + (size_t)(b0 + b) * 128 + iq * 16);
            uint hh[8], ll[8];
#pragma unroll
            for (int q = 0; q < 4; ++q) {
                const float4 v = yp[q];
                const uint h0 = pk(v.x, v.y);
                const uint h1 = pk(v.z, v.w);
                hh[2 * q] = h0;
                hh[2 * q + 1] = h1;
                ll[2 * q] = pk(v.x - blo(h0), v.y - bhif(h0));
                ll[2 * q + 1] = pk(v.z - blo(h1), v.w - bhif(h1));
            }
            char* dh = smc + ATN_Y + b * AROWB + iq * 32;
            char* dl = smc + ATN_YL + b * AROWB + iq * 32;
            *(uint4*)dh = make_uint4(hh[0], hh[1], hh[2], hh[3]);
            *(uint4*)(dh + 16) = make_uint4(hh[4], hh[5], hh[6], hh[7]);
            *(uint4*)dl = make_uint4(ll[0], ll[1], ll[2], ll[3]);
            *(uint4*)(dl + 16) = make_uint4(ll[4], ll[5], ll[6], ll[7]);
        }
        __syncthreads();

        float d0[4] = {0, 0, 0, 0}, d1[4] = {0, 0, 0, 0};
        float d2[4] = {0, 0, 0, 0}, d3[4] = {0, 0, 0, 0};
#pragma unroll
        for (int ki = 0; ki < 8; ++ki) {
            const int off = ki * 32;
            const uint ah0 = *(const uint*)(Yhp + off);
            const uint ah1 = *(const uint*)(Yhp + 8 * AROWB + off);
            const uint ah2 = *(const uint*)(Yhp + off + 16);
            const uint ah3 = *(const uint*)(Yhp + 8 * AROWB + off + 16);
            const uint al0 = *(const uint*)(Ylp + off);
            const uint al1 = *(const uint*)(Ylp + 8 * AROWB + off);
            const uint al2 = *(const uint*)(Ylp + off + 16);
            const uint al3 = *(const uint*)(Ylp + 8 * AROWB + off + 16);
#pragma unroll
            for (int ni = 0; ni < 4; ++ni) {
                float* dd = ni == 0 ? d0 : ni == 1 ? d1 : ni == 2 ? d2 : d3;
                const uint bh0 = *(const uint*)(Bhp + ni * 8 * AROWB + off);
                const uint bh1 = *(const uint*)(Bhp + ni * 8 * AROWB + off + 16);
                const uint bl0 = *(const uint*)(Blp + ni * 8 * AROWB + off);
                const uint bl1 = *(const uint*)(Blp + ni * 8 * AROWB + off + 16);
                mma_bf16(dd, ah0, ah1, ah2, ah3, bh0, bh1);
                mma_bf16(dd, ah0, ah1, ah2, ah3, bl0, bl1);
                mma_bf16(dd, al0, al1, al2, al3, bh0, bh1);
            }
        }
        __syncthreads();

#pragma unroll
        for (int ni = 0; ni < 4; ++ni) {
            const float* dd = ni == 0 ? d0 : ni == 1 ? d1 : ni == 2 ? d2 : d3;
            const int r = mt * 16 + r4;
            const int c = ng * 32 + ni * 8 + cq * 2;
            *(float2*)(sP + r * 132 + c) = make_float2(dd[0], dd[1]);
            *(float2*)(sP + (r + 8) * 132 + c) = make_float2(dd[2], dd[3]);
        }
        __syncthreads();

#pragma unroll
        for (int bb = 0; bb < 4; ++bb) {
            const int b = w * 4 + bb;
            const float4 pv = *(const float4*)(sP + b * 132 + lane * 4);
            const float4* xb = (const float4*)(x + (size_t)(b0 + b) * 512);
#pragma unroll
            for (int s = 0; s < 4; ++s) {
                const float4 xv = xb[s * 32 + lane];
                float d = xv.x * pv.x + xv.y * pv.y + xv.z * pv.z + xv.w * pv.w;
                d += __shfl_xor_sync(0xffffffffu, d, 16);
                d += __shfl_xor_sync(0xffffffffu, d, 8);
                d += __shfl_xor_sync(0xffffffffu, d, 4);
                d += __shfl_xor_sync(0xffffffffu, d, 2);
                d += __shfl_xor_sync(0xffffffffu, d, 1);
                if (lane == 0) sD[b * 4 + s] = d;
            }
        }
        __syncthreads();
        if (t < 64) {
            const float d0s = sD[t * 4], d1s = sD[t * 4 + 1];
            const float d2s = sD[t * 4 + 2], d3s = sD[t * 4 + 3];
            const float mx = fmaxf(fmaxf(d0s, d1s), fmaxf(d2s, d3s));
            const float e0 = expf(d0s - mx), e1 = expf(d1s - mx);
            const float e2 = expf(d2s - mx), e3 = expf(d3s - mx);
            const float inv = 1.f / (e0 + e1 + e2 + e3);
            ((float4*)g_w)[b0 + t] = make_float4(e0 * inv, e1 * inv, e2 * inv, e3 * inv);
        }
    }
}

// ---------------- z kernel: fp16 2-pass (A single, B hi/lo) ----------------
#define ROWB 528
#define SM_AH 0
#define SM_BH 67584
#define SM_BL 101376
#define SM_TOT 135168

__global__ __launch_bounds__(512, 1) void z_kernel(const float* __restrict__ x,
                                                   float* __restrict__ out, int B) {
    extern __shared__ char smc[];
    const int t = threadIdx.x;
    const int lane = t & 31, w = t >> 5;

    for (int i = t; i < 4096; i += 512) {
        const int row = i >> 5, c = i & 31;
        *(uint4*)(smc + SM_AH + row * ROWB + c * 16) = ((const uint4*)g_Mh)[i];
    }

    const int o_base = (w & 7) * 16;
    const int nhalf = w >> 3;
    const int r4 = lane >> 2, cq = lane & 3;
    const float tb0 = g_tb[o_base + r4];
    const float tb1 = g_tb[o_base + r4 + 8];

    const char* Ahp = smc + SM_AH + (o_base + r4) * ROWB + cq * 4;
    const char* Bhp = smc + SM_BH + (nhalf * 32 + r4) * ROWB + cq * 4;
    const char* Blp = smc + SM_BL + (nhalf * 32 + r4) * ROWB + cq * 4;

    const int nch = B >> 5;
    for (int ch = blockIdx.x; ch < nch; ch += gridDim.x) {
        const int b0 = ch << 5;
        __syncthreads();
#pragma unroll
        for (int q = 0; q < 2; ++q) {
            const int b = w + 16 * q;
            const int half = lane >> 4, ko = lane & 15;
            const float2 ws = *(const float2*)(g_w + (size_t)(b0 + b) * 4 + half * 2);
            const float* xp = x + (size_t)(b0 + b) * 512 + half * 256 + ko * 8;
            const float4 xa = *(const float4*)xp;
            const float4 xb2 = *(const float4*)(xp + 4);
            const float4 ya = *(const float4*)(xp + 128);
            const float4 yb = *(const float4*)(xp + 132);
            float vp[8], vm[8];
            const float* xs = (const float*)&xa;
            const float* ys = (const float*)&ya;
#pragma unroll
            for (int jj = 0; jj < 4; ++jj) {
                const float a0 = ws.x * xs[jj], a1 = ws.y * ys[jj];
                vp[jj] = a0 + a1;
                vm[jj] = a0 - a1;
            }
            const float* xs2 = (const float*)&xb2;
            const float* ys2 = (const float*)&yb;
#pragma unroll
            for (int jj = 0; jj < 4; ++jj) {
                const float a0 = ws.x * xs2[jj], a1 = ws.y * ys2[jj];
                vp[4 + jj] = a0 + a1;
                vm[4 + jj] = a0 - a1;
            }
            uint hp[4], hm[4], lp[4], lm[4];
#pragma unroll
            for (int jj = 0; jj < 4; ++jj) {
                hp[jj] = pkh(vp[2 * jj], vp[2 * jj + 1]);
                lp[jj] = pkh(vp[2 * jj] - hlo(hp[jj]), vp[2 * jj + 1] - hhi(hp[jj]));
                hm[jj] = pkh(vm[2 * jj], vm[2 * jj + 1]);
                lm[jj] = pkh(vm[2 * jj] - hlo(hm[jj]), vm[2 * jj + 1] - hhi(hm[jj]));
            }
            const int coff = (half * 128 + ko * 8) * 2;
            char* rp = smc + SM_BH + (2 * b) * ROWB + coff;
            *(uint4*)rp = make_uint4(hp[0], hp[1], hp[2], hp[3]);
            *(uint4*)(rp + ROWB) = make_uint4(hm[0], hm[1], hm[2], hm[3]);
            char* rp2 = smc + SM_BL + (2 * b) * ROWB + coff;
            *(uint4*)rp2 = make_uint4(lp[0], lp[1], lp[2], lp[3]);
            *(uint4*)(rp2 + ROWB) = make_uint4(lm[0], lm[1], lm[2], lm[3]);
        }
        __syncthreads();

        float d0[4] = {0, 0, 0, 0}, d1[4] = {0, 0, 0, 0};
        float d2[4] = {0, 0, 0, 0}, d3[4] = {0, 0, 0, 0};
#pragma unroll 4
        for (int ki = 0; ki < 16; ++ki) {
            const int off = ki * 32;
            const uint ah0 = *(const uint*)(Ahp + off);
            const uint ah1 = *(const uint*)(Ahp + 8 * ROWB + off);
            const uint ah2 = *(const uint*)(Ahp + off + 16);
            const uint ah3 = *(const uint*)(Ahp + 8 * ROWB + off + 16);
#pragma unroll
            for (int ni = 0; ni < 4; ++ni) {
                float* dd = ni == 0 ? d0 : ni == 1 ? d1 : ni == 2 ? d2 : d3;
                const uint bh0 = *(const uint*)(Bhp + ni * 8 * ROWB + off);
                const uint bh1 = *(const uint*)(Bhp + ni * 8 * ROWB + off + 16);
                const uint bl0 = *(const uint*)(Blp + ni * 8 * ROWB + off);
                const uint bl1 = *(const uint*)(Blp + ni * 8 * ROWB + off + 16);
                mma_f16(dd, ah0, ah1, ah2, ah3, bh0, bh1);
                mma_f16(dd, ah0, ah1, ah2, ah3, bl0, bl1);
            }
        }

        const int g = b0 >> 9, dbase = b0 & 511;
#pragma unroll
        for (int ni = 0; ni < 4; ++ni) {
            const float* dd = ni == 0 ? d0 : ni == 1 ? d1 : ni == 2 ? d2 : d3;
            const int b = (nhalf * 4 + ni) * 4 + cq;
            float* op = out + ((size_t)(g * 128 + o_base + r4)) * 1024 + 2 * (dbase + b);
            float e0 = dd[0] + tb0, e1 = dd[1] + tb0;
            float e2 = dd[2] + tb1, e3 = dd[3] + tb1;
            e0 = e0 > 0.f ? e0 : 0.01f * e0;
            e1 = e1 > 0.f ? e1 : 0.01f * e1;
            e2 = e2 > 0.f ? e2 : 0.01f * e2;
            e3 = e3 > 0.f ? e3 : 0.01f * e3;
            *(float2*)op = make_float2(e0, e1);
            *(float2*)(op + 8 * 1024) = make_float2(e2, e3);
        }
    }
}

extern "C" void kernel_launch(void* const* d_in, const int* in_sizes, int n_in,
                              void* d_out, int out_size) {
    const float* x = (const float*)d_in[0];
    const float* y = (const float*)d_in[1];
    const int B = in_sizes[0] / (4 * K);

    cudaFuncSetAttribute(attn_kernel, cudaFuncAttributeMaxDynamicSharedMemorySize, ATN_TOT);
    cudaFuncSetAttribute(z_kernel, cudaFuncAttributeMaxDynamicSharedMemorySize, SM_TOT);

    setup_kernel<<<dim3(K, 3), 256>>>((const float*)d_in[2], (const float*)d_in[3],
                                      (const float*)d_in[4], (const float*)d_in[5],
                                      (const float*)d_in[6], (const float*)d_in[7],
                                      (const float*)d_in[8], (const float*)d_in[9],
                                      (const float*)d_in[10]);
    attn_kernel<<<148, 512, ATN_TOT>>>(x, y, B);
    z_kernel<<<148, 512, SM_TOT>>>(x, (float*)d_out, B);
}

// round 17
// speedup vs baseline: 2.9281x; 1.0204x over previous
#include <cuda_runtime.h>
#include <cuda_bf16.h>
#include <cuda_fp16.h>
#include <cstdint>

#define K 128

typedef unsigned long long ull;
typedef unsigned int uint;

__device__ float g_tb[K];
__device__ float g_w[32768 * 4];
__device__ __align__(16) __half g_Mh[128 * 256];          // Mcat fp16, [o][k]
__device__ __align__(16) __nv_bfloat16 g_ATh[128 * 128];  // A^T bf16 hi, [j][i]
__device__ __align__(16) __nv_bfloat16 g_ATl[128 * 128];  // A^T residual, [j][i]

// ---------------- helpers ----------------
__device__ __forceinline__ uint pk(float lo, float hi) {  // bf16x2
    uint r;
    asm("cvt.rn.bf16x2.f32 %0, %1, %2;" : "=r"(r) : "f"(hi), "f"(lo));
    return r;
}
__device__ __forceinline__ float blo(uint u) { return __uint_as_float(u << 16); }
__device__ __forceinline__ float bhif(uint u) { return __uint_as_float(u & 0xffff0000u); }

__device__ __forceinline__ uint pkh(float lo, float hi) {  // f16x2
    uint r;
    asm("cvt.rn.f16x2.f32 %0, %1, %2;" : "=r"(r) : "f"(hi), "f"(lo));
    return r;
}

__device__ __forceinline__ void mma_bf16(float* d, uint a0, uint a1, uint a2, uint a3,
                                         uint b0, uint b1) {
    asm volatile(
        "mma.sync.aligned.m16n8k16.row.col.f32.bf16.bf16.f32 "
        "{%0,%1,%2,%3}, {%4,%5,%6,%7}, {%8,%9}, {%0,%1,%2,%3};"
        : "+f"(d[0]), "+f"(d[1]), "+f"(d[2]), "+f"(d[3])
        : "r"(a0), "r"(a1), "r"(a2), "r"(a3), "r"(b0), "r"(b1));
}
__device__ __forceinline__ void mma_f16(float* d, uint a0, uint a1, uint a2, uint a3,
                                        uint b0, uint b1) {
    asm volatile(
        "mma.sync.aligned.m16n8k16.row.col.f32.f16.f16.f32 "
        "{%0,%1,%2,%3}, {%4,%5,%6,%7}, {%8,%9}, {%0,%1,%2,%3};"
        : "+f"(d[0]), "+f"(d[1]), "+f"(d[2]), "+f"(d[3])
        : "r"(a0), "r"(a1), "r"(a2), "r"(a3), "r"(b0), "r"(b1));
}

// ---------------- setup: 48 blocks, W cached in smem once ----------------
// grid (16, 3): blockIdx.x = row-group (8 rows), blockIdx.y = matrix (0:A, 1:M0, 2:M1)
__global__ __launch_bounds__(256) void setup_kernel(
    const float* __restrict__ Wq, const float* __restrict__ Wk, const float* __restrict__ Wv,
    const float* __restrict__ conv_w, const float* __restrict__ conv_b,
    const float* __restrict__ gamma, const float* __restrict__ beta,
    const float* __restrict__ mean, const float* __restrict__ var) {
    const int m = blockIdx.y, rg = blockIdx.x, t = threadIdx.x;
    __shared__ float W[128 * 128];
    __shared__ float rows[8][128];
    const float4* Wsrc = (const float4*)((m == 0) ? Wk : Wv);
    for (int i = t; i < 4096; i += 256) ((float4*)W)[i] = Wsrc[i];
    const int r0 = rg * 8;
    if (m == 0) {
        for (int idx = t; idx < 1024; idx += 256) {
            const int rr = idx >> 7, o = idx & 127;
            rows[rr][o] = __ldg(Wq + o * 128 + r0 + rr);
        }
    } else {
        const int off = (m == 2) ? 128 : 0;
        for (int idx = t; idx < 1024; idx += 256) {
            const int rr = idx >> 7, c = idx & 127;
            rows[rr][c] = __ldg(conv_w + (size_t)(r0 + rr) * 256 + off + c);
        }
    }
    __syncthreads();

    const int rr = t >> 5, j0 = (t & 31) * 4;
    float4 acc = make_float4(0.f, 0.f, 0.f, 0.f);
#pragma unroll 8
    for (int o = 0; o < 128; ++o) {
        const float rv = rows[rr][o];
        const float4 wv = *(const float4*)(W + o * 128 + j0);
        acc.x += rv * wv.x;
        acc.y += rv * wv.y;
        acc.z += rv * wv.z;
        acc.w += rv * wv.w;
    }
    const int r = r0 + rr;
    float vals[4] = {acc.x, acc.y, acc.z, acc.w};
    if (m == 0) {
#pragma unroll
        for (int q = 0; q < 4; ++q) {
            const int j = j0 + q;
            const float val = vals[q] * 0.08838834764831845f;
            const __nv_bfloat16 hb = __float2bfloat16(val);
            g_ATh[j * 128 + r] = hb;
            g_ATl[j * 128 + r] = __float2bfloat16(val - __bfloat162float(hb));
        }
    } else {
        const float sc = gamma[r] * rsqrtf(var[r] + 1e-5f);
#pragma unroll
        for (int q = 0; q < 4; ++q) {
            const int kk = j0 + q + ((m == 2) ? 128 : 0);
            g_Mh[r * 256 + kk] = __float2half_rn(vals[q] * sc * 0.7071067811865476f);
        }
        if (m == 1 && (t & 31) == 0) g_tb[r] = (conv_b[r] - mean[r]) * sc + beta[r];
    }
}

// ---------------- attention: HMMA bf16x3 (unchanged, passing) ----------------
#define AROWB 528
#define ATN_ATH 0
#define ATN_ATL 67584
#define ATN_Y 135168
#define ATN_YL 168960
#define ATN_D 202752
#define ATN_TOT 203776

__global__ __launch_bounds__(512, 1) void attn_kernel(const float* __restrict__ x,
                                                      const float* __restrict__ y, int B) {
    extern __shared__ char smc[];
    const int t = threadIdx.x;
    const int lane = t & 31, w = t >> 5;

    for (int i = t; i < 2048; i += 512) {
        const int r = i >> 4, c = i & 15;
        *(uint4*)(smc + ATN_ATH + r * AROWB + c * 16) = ((const uint4*)g_ATh)[i];
        *(uint4*)(smc + ATN_ATL + r * AROWB + c * 16) = ((const uint4*)g_ATl)[i];
    }
    const int mt = w & 3, ng = w >> 2;
    const int r4 = lane >> 2, cq = lane & 3;
    const char* Yhp = smc + ATN_Y + (mt * 16 + r4) * AROWB + cq * 4;
    const char* Ylp = smc + ATN_YL + (mt * 16 + r4) * AROWB + cq * 4;
    const char* Bhp = smc + ATN_ATH + (ng * 32 + r4) * AROWB + cq * 4;
    const char* Blp = smc + ATN_ATL + (ng * 32 + r4) * AROWB + cq * 4;
    float* sP = (float*)(smc + ATN_Y);
    float* sD = (float*)(smc + ATN_D);

    const int nch = B >> 6;
    for (int ch = blockIdx.x; ch < nch; ch += gridDim.x) {
        const int b0 = ch << 6;
        __syncthreads();
        {
            const int b = t >> 3, iq = t & 7;
            const float4* yp = (const float4*)(y + (size_t)(b0 + b) * 128 + iq * 16);
            uint hh[8], ll[8];
#pragma unroll
            for (int q = 0; q < 4; ++q) {
                const float4 v = yp[q];
                const uint h0 = pk(v.x, v.y);
                const uint h1 = pk(v.z, v.w);
                hh[2 * q] = h0;
                hh[2 * q + 1] = h1;
                ll[2 * q] = pk(v.x - blo(h0), v.y - bhif(h0));
                ll[2 * q + 1] = pk(v.z - blo(h1), v.w - bhif(h1));
            }
            char* dh = smc + ATN_Y + b * AROWB + iq * 32;
            char* dl = smc + ATN_YL + b * AROWB + iq * 32;
            *(uint4*)dh = make_uint4(hh[0], hh[1], hh[2], hh[3]);
            *(uint4*)(dh + 16) = make_uint4(hh[4], hh[5], hh[6], hh[7]);
            *(uint4*)dl = make_uint4(ll[0], ll[1], ll[2], ll[3]);
            *(uint4*)(dl + 16) = make_uint4(ll[4], ll[5], ll[6], ll[7]);
        }
        __syncthreads();

        float d0[4] = {0, 0, 0, 0}, d1[4] = {0, 0, 0, 0};
        float d2[4] = {0, 0, 0, 0}, d3[4] = {0, 0, 0, 0};
#pragma unroll
        for (int ki = 0; ki < 8; ++ki) {
            const int off = ki * 32;
            const uint ah0 = *(const uint*)(Yhp + off);
            const uint ah1 = *(const uint*)(Yhp + 8 * AROWB + off);
            const uint ah2 = *(const uint*)(Yhp + off + 16);
            const uint ah3 = *(const uint*)(Yhp + 8 * AROWB + off + 16);
            const uint al0 = *(const uint*)(Ylp + off);
            const uint al1 = *(const uint*)(Ylp + 8 * AROWB + off);
            const uint al2 = *(const uint*)(Ylp + off + 16);
            const uint al3 = *(const uint*)(Ylp + 8 * AROWB + off + 16);
#pragma unroll
            for (int ni = 0; ni < 4; ++ni) {
                float* dd = ni == 0 ? d0 : ni == 1 ? d1 : ni == 2 ? d2 : d3;
                const uint bh0 = *(const uint*)(Bhp + ni * 8 * AROWB + off);
                const uint bh1 = *(const uint*)(Bhp + ni * 8 * AROWB + off + 16);
                const uint bl0 = *(const uint*)(Blp + ni * 8 * AROWB + off);
                const uint bl1 = *(const uint*)(Blp + ni * 8 * AROWB + off + 16);
                mma_bf16(dd, ah0, ah1, ah2, ah3, bh0, bh1);
                mma_bf16(dd, ah0, ah1, ah2, ah3, bl0, bl1);
                mma_bf16(dd, al0, al1, al2, al3, bh0, bh1);
            }
        }
        __syncthreads();

#pragma unroll
        for (int ni = 0; ni < 4; ++ni) {
            const float* dd = ni == 0 ? d0 : ni == 1 ? d1 : ni == 2 ? d2 : d3;
            const int r = mt * 16 + r4;
            const int c = ng * 32 + ni * 8 + cq * 2;
            *(float2*)(sP + r * 132 + c) = make_float2(dd[0], dd[1]);
            *(float2*)(sP + (r + 8) * 132 + c) = make_float2(dd[2], dd[3]);
        }
        __syncthreads();

#pragma unroll
        for (int bb = 0; bb < 4; ++bb) {
            const int b = w * 4 + bb;
            const float4 pv = *(const float4*)(sP + b * 132 + lane * 4);
            const float4* xb = (const float4*)(x + (size_t)(b0 + b) * 512);
#pragma unroll
            for (int s = 0; s < 4; ++s) {
                const float4 xv = xb[s * 32 + lane];
                float d = xv.x * pv.x + xv.y * pv.y + xv.z * pv.z + xv.w * pv.w;
                d += __shfl_xor_sync(0xffffffffu, d, 16);
                d += __shfl_xor_sync(0xffffffffu, d, 8);
                d += __shfl_xor_sync(0xffffffffu, d, 4);
                d += __shfl_xor_sync(0xffffffffu, d, 2);
                d += __shfl_xor_sync(0xffffffffu, d, 1);
                if (lane == 0) sD[b * 4 + s] = d;
            }
        }
        __syncthreads();
        if (t < 64) {
            const float d0s = sD[t * 4], d1s = sD[t * 4 + 1];
            const float d2s = sD[t * 4 + 2], d3s = sD[t * 4 + 3];
            const float mx = fmaxf(fmaxf(d0s, d1s), fmaxf(d2s, d3s));
            const float e0 = expf(d0s - mx), e1 = expf(d1s - mx);
            const float e2 = expf(d2s - mx), e3 = expf(d3s - mx);
            const float inv = 1.f / (e0 + e1 + e2 + e3);
            ((float4*)g_w)[b0 + t] = make_float4(e0 * inv, e1 * inv, e2 * inv, e3 * inv);
        }
    }
}

// ---------------- z kernel: fp16 single-pass ----------------
#define ROWB 528
#define SM_AH 0
#define SM_BH 67584
#define SM_TOT 101376

__global__ __launch_bounds__(512, 1) void z_kernel(const float* __restrict__ x,
                                                   float* __restrict__ out, int B) {
    extern __shared__ char smc[];
    const int t = threadIdx.x;
    const int lane = t & 31, w = t >> 5;

    for (int i = t; i < 4096; i += 512) {
        const int row = i >> 5, c = i & 31;
        *(uint4*)(smc + SM_AH + row * ROWB + c * 16) = ((const uint4*)g_Mh)[i];
    }

    const int o_base = (w & 7) * 16;
    const int nhalf = w >> 3;
    const int r4 = lane >> 2, cq = lane & 3;
    const float tb0 = g_tb[o_base + r4];
    const float tb1 = g_tb[o_base + r4 + 8];

    const char* Ahp = smc + SM_AH + (o_base + r4) * ROWB + cq * 4;
    const char* Bhp = smc + SM_BH + (nhalf * 32 + r4) * ROWB + cq * 4;

    const int nch = B >> 5;
    for (int ch = blockIdx.x; ch < nch; ch += gridDim.x) {
        const int b0 = ch << 5;
        __syncthreads();
#pragma unroll
        for (int q = 0; q < 2; ++q) {
            const int b = w + 16 * q;
            const int half = lane >> 4, ko = lane & 15;
            const float2 ws = *(const float2*)(g_w + (size_t)(b0 + b) * 4 + half * 2);
            const float* xp = x + (size_t)(b0 + b) * 512 + half * 256 + ko * 8;
            const float4 xa = *(const float4*)xp;
            const float4 xb2 = *(const float4*)(xp + 4);
            const float4 ya = *(const float4*)(xp + 128);
            const float4 yb = *(const float4*)(xp + 132);
            float vp[8], vm[8];
            const float* xs = (const float*)&xa;
            const float* ys = (const float*)&ya;
#pragma unroll
            for (int jj = 0; jj < 4; ++jj) {
                const float a0 = ws.x * xs[jj], a1 = ws.y * ys[jj];
                vp[jj] = a0 + a1;
                vm[jj] = a0 - a1;
            }
            const float* xs2 = (const float*)&xb2;
            const float* ys2 = (const float*)&yb;
#pragma unroll
            for (int jj = 0; jj < 4; ++jj) {
                const float a0 = ws.x * xs2[jj], a1 = ws.y * ys2[jj];
                vp[4 + jj] = a0 + a1;
                vm[4 + jj] = a0 - a1;
            }
            uint hp[4], hm[4];
#pragma unroll
            for (int jj = 0; jj < 4; ++jj) {
                hp[jj] = pkh(vp[2 * jj], vp[2 * jj + 1]);
                hm[jj] = pkh(vm[2 * jj], vm[2 * jj + 1]);
            }
            const int coff = (half * 128 + ko * 8) * 2;
            char* rp = smc + SM_BH + (2 * b) * ROWB + coff;
            *(uint4*)rp = make_uint4(hp[0], hp[1], hp[2], hp[3]);
            *(uint4*)(rp + ROWB) = make_uint4(hm[0], hm[1], hm[2], hm[3]);
        }
        __syncthreads();

        float d0[4] = {0, 0, 0, 0}, d1[4] = {0, 0, 0, 0};
        float d2[4] = {0, 0, 0, 0}, d3[4] = {0, 0, 0, 0};
#pragma unroll 4
        for (int ki = 0; ki < 16; ++ki) {
            const int off = ki * 32;
            const uint ah0 = *(const uint*)(Ahp + off);
            const uint ah1 = *(const uint*)(Ahp + 8 * ROWB + off);
            const uint ah2 = *(const uint*)(Ahp + off + 16);
            const uint ah3 = *(const uint*)(Ahp + 8 * ROWB + off + 16);
#pragma unroll
            for (int ni = 0; ni < 4; ++ni) {
                float* dd = ni == 0 ? d0 : ni == 1 ? d1 : ni == 2 ? d2 : d3;
                const uint bh0 = *(const uint*)(Bhp + ni * 8 * ROWB + off);
                const uint bh1 = *(const uint*)(Bhp + ni * 8 * ROWB + off + 16);
                mma_f16(dd, ah0, ah1, ah2, ah3, bh0, bh1);
            }
        }

        const int g = b0 >> 9, dbase = b0 & 511;
#pragma unroll
        for (int ni = 0; ni < 4; ++ni) {
            const float* dd = ni == 0 ? d0 : ni == 1 ? d1 : ni == 2 ? d2 : d3;
            const int b = (nhalf * 4 + ni) * 4 + cq;
            float* op = out + ((size_t)(g * 128 + o_base + r4)) * 1024 + 2 * (dbase + b);
            float e0 = dd[0] + tb0, e1 = dd[1] + tb0;
            float e2 = dd[2] + tb1, e3 = dd[3] + tb1;
            e0 = e0 > 0.f ? e0 : 0.01f * e0;
            e1 = e1 > 0.f ? e1 : 0.01f * e1;
            e2 = e2 > 0.f ? e2 : 0.01f * e2;
            e3 = e3 > 0.f ? e3 : 0.01f * e3;
            *(float2*)op = make_float2(e0, e1);
            *(float2*)(op + 8 * 1024) = make_float2(e2, e3);
        }
    }
}

extern "C" void kernel_launch(void* const* d_in, const int* in_sizes, int n_in,
                              void* d_out, int out_size) {
    const float* x = (const float*)d_in[0];
    const float* y = (const float*)d_in[1];
    const int B = in_sizes[0] / (4 * K);

    cudaFuncSetAttribute(attn_kernel, cudaFuncAttributeMaxDynamicSharedMemorySize, ATN_TOT);
    cudaFuncSetAttribute(z_kernel, cudaFuncAttributeMaxDynamicSharedMemorySize, SM_TOT);

    setup_kernel<<<dim3(16, 3), 256>>>((const float*)d_in[2], (const float*)d_in[3],
                                       (const float*)d_in[4], (const float*)d_in[5],
                                       (const float*)d_in[6], (const float*)d_in[7],
                                       (const float*)d_in[8], (const float*)d_in[9],
                                       (const float*)d_in[10]);
    attn_kernel<<<148, 512, ATN_TOT>>>(x, y, B);
    z_kernel<<<148, 512, SM_TOT>>>(x, (float*)d_out, B);
}